// round 11
// baseline (speedup 1.0000x reference)
#include <cuda_runtime.h>
#include <cuda_bf16.h>
#include <cstdint>

// R11: identical to R10 — that round failed on GPU acquisition (infra), not the kernel.

#define NN 50000
#define NE 800000
#define NG 64

// ---------------- scratch (device globals; no allocation allowed) ----------
__device__ float g_P [NN * 256];   // x @ W1a[0:128,:] + b1a
__device__ float g_T [NN * 256];   // x @ W2a[0:128,:] + b2a
__device__ float g_UG[NG * 256];   // u @ W2a[256:384,:]
__device__ float g_sum[NN * 128];  // scatter-sum of edge MLP output
__device__ int   g_cnt[NN];        // in-degree
// split-bf16 transposed weights for the tensor-core edge path
__device__ __nv_bfloat16 g_B1hi[256 * 128];  // [n][k] = W1a[128+k][n] (edge_attr half)
__device__ __nv_bfloat16 g_B1lo[256 * 128];
__device__ __nv_bfloat16 g_B2hi[128 * 256];  // [n][k] = W1b[k][n]
__device__ __nv_bfloat16 g_B2lo[128 * 256];

// ---------------- packed fp32x2 helpers (scalar kernels) --------------------
__device__ __forceinline__ unsigned long long ffma2(unsigned long long a,
                                                    unsigned long long b,
                                                    unsigned long long c) {
    unsigned long long d;
    asm("fma.rn.f32x2 %0, %1, %2, %3;" : "=l"(d) : "l"(a), "l"(b), "l"(c));
    return d;
}
__device__ __forceinline__ unsigned long long dup2(float x) {
    unsigned long long d; unsigned int u = __float_as_uint(x);
    asm("mov.b64 %0, {%1, %1};" : "=l"(d) : "r"(u));
    return d;
}
__device__ __forceinline__ float2 ull2f2(unsigned long long v) {
    float2 f;
    f.x = __uint_as_float((unsigned int)(v & 0xFFFFFFFFULL));
    f.y = __uint_as_float((unsigned int)(v >> 32));
    return f;
}

// ---------------- mma.sync helpers ------------------------------------------
__device__ __forceinline__ uint32_t smem_u32(const void* p) {
    uint32_t a;
    asm("{ .reg .u64 t; cvta.to.shared.u64 t, %1; cvt.u32.u64 %0, t; }"
        : "=r"(a) : "l"(p));
    return a;
}
__device__ __forceinline__ void ldmx4(uint32_t& r0, uint32_t& r1,
                                      uint32_t& r2, uint32_t& r3, uint32_t addr) {
    asm volatile("ldmatrix.sync.aligned.m8n8.x4.shared.b16 {%0,%1,%2,%3}, [%4];"
                 : "=r"(r0), "=r"(r1), "=r"(r2), "=r"(r3) : "r"(addr));
}
__device__ __forceinline__ void mma_bf16(float c[4], const uint32_t a[4],
                                         const uint32_t b[2]) {
    asm volatile(
        "mma.sync.aligned.m16n8k16.row.col.f32.bf16.bf16.f32 "
        "{%0,%1,%2,%3}, {%4,%5,%6,%7}, {%8,%9}, {%0,%1,%2,%3};"
        : "+f"(c[0]), "+f"(c[1]), "+f"(c[2]), "+f"(c[3])
        : "r"(a[0]), "r"(a[1]), "r"(a[2]), "r"(a[3]), "r"(b[0]), "r"(b[1]));
}
// split fp32 pair -> packed bf16x2 hi + residual lo (x -> low half)
__device__ __forceinline__ void split2(float2 v, uint32_t& hi, uint32_t& lo) {
    asm("cvt.rn.bf16x2.f32 %0, %1, %2;" : "=r"(hi) : "f"(v.y), "f"(v.x));
    float hx = __uint_as_float(hi << 16);
    float hy = __uint_as_float(hi & 0xFFFF0000u);
    float lx = v.x - hx, ly = v.y - hy;
    asm("cvt.rn.bf16x2.f32 %0, %1, %2;" : "=r"(lo) : "f"(ly), "f"(lx));
}
__device__ __forceinline__ float bfr(float v) {
    return __bfloat162float(__float2bfloat16_rn(v));
}

// ---------------- edge kernel smem layout (bytes) ---------------------------
// sA  fp32 [64][136]   34816      (EA tile)
// sH  fp32 [64][264]   67584      (hidden relu output)
// sBh bf16 [256][40]   20480      (B chunk hi, stride 40 bf16 = 80 B)
// sBl bf16 [256][40]   20480
// sEi int[64], sCd int[64], sB1b float[128]
#define SM_A   0
#define SM_H   34816
#define SM_BH  102400
#define SM_BL  122880
#define SM_EI  143360
#define SM_CD  143616
#define SM_B1B 143872
#define SMEM_E 144384

// ============================================================================
// Tensor-core edge kernel: 64 edges/CTA, 8 warps (wm = wid&1, wn = wid>>1)
//   C1 = EA @ B1^T (K=128) ; h = relu(C1 + P[row]) -> sH
//   C2 = h @ B2^T (K=256)  ; scatter-add(C2 + b1b), degree count
// ============================================================================
__global__ __launch_bounds__(256, 1)
void edge_tc(const float* __restrict__ ea,
             const int*   __restrict__ ei,
             const float* __restrict__ b1b) {
    extern __shared__ char sm[];
    float* sA  = (float*)(sm + SM_A);
    float* sH  = (float*)(sm + SM_H);
    int*   sEi = (int*)(sm + SM_EI);
    int*   sCd = (int*)(sm + SM_CD);
    float* sB1b= (float*)(sm + SM_B1B);
    const uint32_t sbase = smem_u32(sm);
    const uint32_t uBH = sbase + SM_BH, uBL = sbase + SM_BL;

    const int tid = threadIdx.x, lane = tid & 31, wid = tid >> 5;
    const int e0 = blockIdx.x * 64;
    const int wm = wid & 1, wn = wid >> 1;
    const int rbase = lane >> 2, cpos = 2 * (lane & 3);

    if (tid < 64) { sEi[tid] = ei[e0 + tid]; sCd[tid] = ei[NE + e0 + tid]; }
    if (tid < 128) sB1b[tid] = b1b[tid];

    // EA tile -> sA fp32 [64][136]
    for (int idx = tid; idx < 2048; idx += 256) {
        int m = idx >> 5, q = idx & 31;
        float4 v = ((const float4*)(ea + (size_t)(e0 + m) * 128))[q];
        *(float4*)(sA + m * 136 + q * 4) = v;
    }

    // ---------------- phase 1: C1[64][256] = EA @ B1^T ----------------
    float c1[2][8][4];
#pragma unroll
    for (int mt = 0; mt < 2; mt++)
#pragma unroll
        for (int nt = 0; nt < 8; nt++)
#pragma unroll
            for (int q = 0; q < 4; q++) c1[mt][nt][q] = 0.f;

    // ldmatrix lane addressing pieces
    const int g = lane >> 3, r8 = lane & 7;
    const int gk = (g & 1) << 3;          // k offset 0/8
    const int gn = (g >> 1) << 3;         // n offset 0/8

    for (int kc = 0; kc < 4; kc++) {      // K chunks of 32
        __syncthreads();
        {   // stage B1 chunk [256n][32k] hi/lo (1 row/thread, 64 B each)
            const uint4* srh = (const uint4*)(g_B1hi + tid * 128 + kc * 32);
            const uint4* srl = (const uint4*)(g_B1lo + tid * 128 + kc * 32);
            uint4* dh = (uint4*)(sm + SM_BH + tid * 80);
            uint4* dl = (uint4*)(sm + SM_BL + tid * 80);
#pragma unroll
            for (int q = 0; q < 4; q++) { dh[q] = srh[q]; dl[q] = srl[q]; }
        }
        __syncthreads();
#pragma unroll
        for (int ks = 0; ks < 2; ks++) {
            const int kg = kc * 32 + ks * 16;
            uint32_t ah[2][4], al[2][4];
#pragma unroll
            for (int mt = 0; mt < 2; mt++) {
                const float* base = sA + (wm * 32 + mt * 16 + rbase) * 136 + kg + cpos;
                split2(*(const float2*)(base),               ah[mt][0], al[mt][0]);
                split2(*(const float2*)(base + 8 * 136),     ah[mt][1], al[mt][1]);
                split2(*(const float2*)(base + 8),           ah[mt][2], al[mt][2]);
                split2(*(const float2*)(base + 8 * 136 + 8), ah[mt][3], al[mt][3]);
            }
            uint32_t bh[8][2], bl[8][2];
            const uint32_t klb = (uint32_t)(ks * 16 + gk) * 2;
#pragma unroll
            for (int ntp = 0; ntp < 4; ntp++) {
                uint32_t off = (uint32_t)(wn * 64 + ntp * 16 + gn + r8) * 80 + klb;
                ldmx4(bh[2*ntp][0], bh[2*ntp][1], bh[2*ntp+1][0], bh[2*ntp+1][1], uBH + off);
                ldmx4(bl[2*ntp][0], bl[2*ntp][1], bl[2*ntp+1][0], bl[2*ntp+1][1], uBL + off);
            }
#pragma unroll
            for (int mt = 0; mt < 2; mt++)
#pragma unroll
                for (int nt = 0; nt < 8; nt++) {
                    mma_bf16(c1[mt][nt], ah[mt], bh[nt]);
                    mma_bf16(c1[mt][nt], ah[mt], bl[nt]);
                    mma_bf16(c1[mt][nt], al[mt], bh[nt]);
                }
        }
    }

    // ---------------- epilogue 1: h = relu(C1 + P[row]) -> sH ----------------
#pragma unroll
    for (int mt = 0; mt < 2; mt++) {
        int r0 = wm * 32 + mt * 16 + rbase, r1 = r0 + 8;
        const float* P0 = g_P + (size_t)sEi[r0] * 256;
        const float* P1 = g_P + (size_t)sEi[r1] * 256;
#pragma unroll
        for (int nt = 0; nt < 8; nt++) {
            int col = wn * 64 + nt * 8 + cpos;
            float2 q0 = *(const float2*)(P0 + col);
            float2 q1 = *(const float2*)(P1 + col);
            float2 v0, v1;
            v0.x = fmaxf(c1[mt][nt][0] + q0.x, 0.f);
            v0.y = fmaxf(c1[mt][nt][1] + q0.y, 0.f);
            v1.x = fmaxf(c1[mt][nt][2] + q1.x, 0.f);
            v1.y = fmaxf(c1[mt][nt][3] + q1.y, 0.f);
            *(float2*)(sH + r0 * 264 + col) = v0;
            *(float2*)(sH + r1 * 264 + col) = v1;
        }
    }

    // ---------------- phase 2: C2[64][128] = h @ B2^T (K=256) ----------------
    float c2[2][4][4];
#pragma unroll
    for (int mt = 0; mt < 2; mt++)
#pragma unroll
        for (int nt = 0; nt < 4; nt++)
#pragma unroll
            for (int q = 0; q < 4; q++) c2[mt][nt][q] = 0.f;

    for (int kc = 0; kc < 8; kc++) {
        __syncthreads();   // guards sH writes (first iter) and sB reuse
        {   // stage B2 chunk [128n][32k] hi/lo (2 threads/row-copy)
            int rown = tid & 127, half = tid >> 7;
            const uint4* src = (const uint4*)((half ? g_B2lo : g_B2hi) + rown * 256 + kc * 32);
            uint4* dst = (uint4*)(sm + (half ? SM_BL : SM_BH) + rown * 80);
#pragma unroll
            for (int q = 0; q < 4; q++) dst[q] = src[q];
        }
        __syncthreads();
#pragma unroll
        for (int ks = 0; ks < 2; ks++) {
            const int kg = kc * 32 + ks * 16;
            uint32_t ah[2][4], al[2][4];
#pragma unroll
            for (int mt = 0; mt < 2; mt++) {
                const float* base = sH + (wm * 32 + mt * 16 + rbase) * 264 + kg + cpos;
                split2(*(const float2*)(base),               ah[mt][0], al[mt][0]);
                split2(*(const float2*)(base + 8 * 264),     ah[mt][1], al[mt][1]);
                split2(*(const float2*)(base + 8),           ah[mt][2], al[mt][2]);
                split2(*(const float2*)(base + 8 * 264 + 8), ah[mt][3], al[mt][3]);
            }
            uint32_t bh[4][2], bl[4][2];
            const uint32_t klb = (uint32_t)(ks * 16 + gk) * 2;
#pragma unroll
            for (int ntp = 0; ntp < 2; ntp++) {
                uint32_t off = (uint32_t)(wn * 32 + ntp * 16 + gn + r8) * 80 + klb;
                ldmx4(bh[2*ntp][0], bh[2*ntp][1], bh[2*ntp+1][0], bh[2*ntp+1][1], uBH + off);
                ldmx4(bl[2*ntp][0], bl[2*ntp][1], bl[2*ntp+1][0], bl[2*ntp+1][1], uBL + off);
            }
#pragma unroll
            for (int mt = 0; mt < 2; mt++)
#pragma unroll
                for (int nt = 0; nt < 4; nt++) {
                    mma_bf16(c2[mt][nt], ah[mt], bh[nt]);
                    mma_bf16(c2[mt][nt], ah[mt], bl[nt]);
                    mma_bf16(c2[mt][nt], al[mt], bh[nt]);
                }
        }
    }

    // ---------------- epilogue 2: scatter-add + degree ----------------
#pragma unroll
    for (int mt = 0; mt < 2; mt++) {
        int r0 = wm * 32 + mt * 16 + rbase, r1 = r0 + 8;
        float* s0 = g_sum + (size_t)sCd[r0] * 128;
        float* s1 = g_sum + (size_t)sCd[r1] * 128;
#pragma unroll
        for (int nt = 0; nt < 4; nt++) {
            int col = wn * 32 + nt * 8 + cpos;
            atomicAdd(s0 + col,     c2[mt][nt][0] + sB1b[col]);
            atomicAdd(s0 + col + 1, c2[mt][nt][1] + sB1b[col + 1]);
            atomicAdd(s1 + col,     c2[mt][nt][2] + sB1b[col]);
            atomicAdd(s1 + col + 1, c2[mt][nt][3] + sB1b[col + 1]);
        }
    }
    if (wn == 0 && (lane & 3) == 0) {
#pragma unroll
        for (int q = 0; q < 4; q++)
            atomicAdd(&g_cnt[sCd[wm * 32 + q * 8 + rbase]], 1);
    }
}

// ============================================================================
// prep: transposed split-bf16 weights
// ============================================================================
__global__ void prep_w(const float* __restrict__ W1a, const float* __restrict__ W1b) {
    int i = blockIdx.x * blockDim.x + threadIdx.x;
    int st = gridDim.x * blockDim.x;
    for (int idx = i; idx < 256 * 128; idx += st) {
        int n = idx >> 7, k = idx & 127;
        float v = W1a[(128 + k) * 256 + n];
        float h = bfr(v);
        g_B1hi[idx] = __float2bfloat16_rn(v);
        g_B1lo[idx] = __float2bfloat16_rn(v - h);
    }
    for (int idx = i; idx < 128 * 256; idx += st) {
        int n = idx >> 8, k = idx & 255;
        float v = W1b[k * 128 + n];
        float h = bfr(v);
        g_B2hi[idx] = __float2bfloat16_rn(v);
        g_B2lo[idx] = __float2bfloat16_rn(v - h);
    }
}

// ---------------- scalar-path shared-memory layout (floats) -----------------
#define SA_STRIDE  132
#define SA_FLOATS  (64 * SA_STRIDE)
#define SWC_OFF    SA_FLOATS
#define SH1_STRIDE 258
#define SH1_FLOATS (64 * SH1_STRIDE)
#define SW2_OFF    SH1_FLOATS
#define SMEM_FLOATS 20736
#define SMEM_BYTES  (SMEM_FLOATS * 4)

__device__ __forceinline__ void p1_chunk(const float* __restrict__ sA,
                                         const float* __restrict__ sWc,
                                         unsigned long long acc[4][8],
                                         int kb, int tx, int ty) {
#pragma unroll 4
    for (int k2 = 0; k2 < 32; k2++) {
        unsigned long long a2[4];
#pragma unroll
        for (int i = 0; i < 4; i++)
            a2[i] = dup2(sA[(ty * 4 + i) * SA_STRIDE + kb + k2]);
        const float* wr = sWc + k2 * 256 + tx * 2;
#pragma unroll
        for (int j = 0; j < 8; j++) {
            unsigned long long w2 = *(const unsigned long long*)(wr + j * 32);
#pragma unroll
            for (int i = 0; i < 4; i++) acc[i][j] = ffma2(a2[i], w2, acc[i][j]);
        }
    }
}

__device__ __forceinline__ void p2_chunk(const float* __restrict__ sH1,
                                         const float* __restrict__ sW2,
                                         unsigned long long acc2[4][4],
                                         int kb, int tx, int ty) {
#pragma unroll 4
    for (int k2 = 0; k2 < 32; k2 += 2) {
        unsigned long long alo[4], ahi[4];
#pragma unroll
        for (int i = 0; i < 4; i++) {
            float2 af = *(const float2*)(sH1 + (ty * 4 + i) * SH1_STRIDE + kb + k2);
            alo[i] = dup2(af.x);
            ahi[i] = dup2(af.y);
        }
#pragma unroll
        for (int j = 0; j < 4; j++) {
            unsigned long long wlo = *(const unsigned long long*)(sW2 + k2 * 128 + j * 32 + tx * 2);
            unsigned long long whi = *(const unsigned long long*)(sW2 + (k2 + 1) * 128 + j * 32 + tx * 2);
#pragma unroll
            for (int i = 0; i < 4; i++) {
                acc2[i][j] = ffma2(alo[i], wlo, acc2[i][j]);
                acc2[i][j] = ffma2(ahi[i], whi, acc2[i][j]);
            }
        }
    }
}

// Pre-GEMM: out[M,256] = A[M,128] @ W[128,256] (+ bias)
__global__ __launch_bounds__(256, 2)
void gemm_k128(const float* __restrict__ A, int M,
               const float* __restrict__ W,
               const float* __restrict__ bias,
               float* __restrict__ out) {
    extern __shared__ float smemf[];
    float* sA  = smemf;
    float* sWc = smemf + SWC_OFF;
    int tid = threadIdx.x;
    int tx = tid & 15, ty = tid >> 4;
    int m0 = blockIdx.x * 64;

    for (int idx = tid; idx < 2048; idx += 256) {
        int m = idx >> 5, kq = idx & 31;
        int gm = m0 + m;
        float4 v = make_float4(0.f, 0.f, 0.f, 0.f);
        if (gm < M) v = ((const float4*)(A + (size_t)gm * 128))[kq];
        *(float4*)(sA + m * SA_STRIDE + kq * 4) = v;
    }

    unsigned long long acc[4][8];
#pragma unroll
    for (int i = 0; i < 4; i++)
#pragma unroll
        for (int j = 0; j < 8; j++) acc[i][j] = 0ULL;

    for (int kb = 0; kb < 128; kb += 32) {
        __syncthreads();
        const float4* wsrc = (const float4*)(W + (size_t)kb * 256);
        for (int idx = tid; idx < 2048; idx += 256)
            ((float4*)sWc)[idx] = wsrc[idx];
        __syncthreads();
        p1_chunk(sA, sWc, acc, kb, tx, ty);
    }

#pragma unroll
    for (int i = 0; i < 4; i++) {
        int gm = m0 + ty * 4 + i;
        if (gm >= M) continue;
        float* orow = out + (size_t)gm * 256;
#pragma unroll
        for (int j = 0; j < 8; j++) {
            int c = j * 32 + tx * 2;
            float2 v = ull2f2(acc[i][j]);
            if (bias) { v.x += bias[c]; v.y += bias[c + 1]; }
            *(float2*)(orow + c) = v;
        }
    }
}

// node kernel: out = relu(agg@W2a_mid + T + UG[batch]) @ W2b + b2b
__global__ __launch_bounds__(256, 2)
void node_kernel(const int* __restrict__ batch,
                 const float* __restrict__ W2a,
                 const float* __restrict__ W2b,
                 const float* __restrict__ b2b,
                 float* __restrict__ out) {
    extern __shared__ float smemf[];
    float* sA  = smemf;
    float* sWc = smemf + SWC_OFF;
    int tid = threadIdx.x;
    int tx = tid & 15, ty = tid >> 4;
    int m0 = blockIdx.x * 64;

    for (int idx = tid; idx < 2048; idx += 256) {
        int m = idx >> 5, kq = idx & 31;
        int gm = m0 + m;
        float4 v = make_float4(0.f, 0.f, 0.f, 0.f);
        if (gm < NN) {
            float sc = 1.0f / fmaxf((float)g_cnt[gm], 1.0f);
            float4 s = ((const float4*)(g_sum + (size_t)gm * 128))[kq];
            v.x = s.x * sc; v.y = s.y * sc; v.z = s.z * sc; v.w = s.w * sc;
        }
        *(float4*)(sA + m * SA_STRIDE + kq * 4) = v;
    }

    unsigned long long acc[4][8];
#pragma unroll
    for (int i = 0; i < 4; i++)
#pragma unroll
        for (int j = 0; j < 8; j++) acc[i][j] = 0ULL;

    const float* Wm = W2a + 128 * 256;
    for (int kb = 0; kb < 128; kb += 32) {
        __syncthreads();
        const float4* wsrc = (const float4*)(Wm + (size_t)kb * 256);
        for (int idx = tid; idx < 2048; idx += 256)
            ((float4*)sWc)[idx] = wsrc[idx];
        __syncthreads();
        p1_chunk(sA, sWc, acc, kb, tx, ty);
    }
    __syncthreads();

    float* sH1 = smemf;
#pragma unroll
    for (int i = 0; i < 4; i++) {
        int gm = m0 + ty * 4 + i;
        float* hrow = sH1 + (ty * 4 + i) * SH1_STRIDE;
        if (gm < NN) {
            const float* Trow = g_T + (size_t)gm * 256;
            const float* Urow = g_UG + (size_t)batch[gm] * 256;
#pragma unroll
            for (int j = 0; j < 8; j++) {
                int c = j * 32 + tx * 2;
                float2 v = ull2f2(acc[i][j]);
                float2 t = *(const float2*)(Trow + c);
                float2 g = *(const float2*)(Urow + c);
                v.x = fmaxf(v.x + t.x + g.x, 0.f);
                v.y = fmaxf(v.y + t.y + g.y, 0.f);
                *(float2*)(hrow + c) = v;
            }
        } else {
#pragma unroll
            for (int j = 0; j < 8; j++) {
                int c = j * 32 + tx * 2;
                *(float2*)(hrow + c) = make_float2(0.f, 0.f);
            }
        }
    }

    float* sW2 = smemf + SW2_OFF;
    unsigned long long acc2[4][4];
#pragma unroll
    for (int i = 0; i < 4; i++)
#pragma unroll
        for (int j = 0; j < 4; j++) acc2[i][j] = 0ULL;

    for (int kb = 0; kb < 256; kb += 32) {
        __syncthreads();
        const float4* wsrc = (const float4*)(W2b + (size_t)kb * 128);
        for (int idx = tid; idx < 1024; idx += 256)
            ((float4*)sW2)[idx] = wsrc[idx];
        __syncthreads();
        p2_chunk(sH1, sW2, acc2, kb, tx, ty);
    }

#pragma unroll
    for (int i = 0; i < 4; i++) {
        int gm = m0 + ty * 4 + i;
        if (gm >= NN) continue;
        float* orow = out + (size_t)gm * 128;
#pragma unroll
        for (int j = 0; j < 4; j++) {
            int c = j * 32 + tx * 2;
            float2 v = ull2f2(acc2[i][j]);
            v.x += b2b[c];
            v.y += b2b[c + 1];
            *(float2*)(orow + c) = v;
        }
    }
}

// ============================================================================
__global__ void zero_kernel() {
    int idx = blockIdx.x * blockDim.x + threadIdx.x;
    int stride = gridDim.x * blockDim.x;
    float4 z = make_float4(0.f, 0.f, 0.f, 0.f);
    for (int i = idx; i < NN * 32; i += stride) ((float4*)g_sum)[i] = z;
    for (int i = idx; i < NN; i += stride) g_cnt[i] = 0;
}

// ============================================================================
extern "C" void kernel_launch(void* const* d_in, const int* in_sizes, int n_in,
                              void* d_out, int out_size) {
    const float* x     = (const float*)d_in[0];
    const int*   ei    = (const int*)d_in[1];     // int32 (JAX x64 disabled)
    const float* ea    = (const float*)d_in[2];
    const float* u     = (const float*)d_in[3];
    const int*   batch = (const int*)d_in[4];
    const float* W1a   = (const float*)d_in[5];
    const float* b1a   = (const float*)d_in[6];
    const float* W1b   = (const float*)d_in[7];
    const float* b1b   = (const float*)d_in[8];
    const float* W2a   = (const float*)d_in[9];
    const float* b2a   = (const float*)d_in[10];
    const float* W2b   = (const float*)d_in[11];
    const float* b2b   = (const float*)d_in[12];
    float* out = (float*)d_out;

    cudaFuncSetAttribute(gemm_k128,   cudaFuncAttributeMaxDynamicSharedMemorySize, SMEM_BYTES);
    cudaFuncSetAttribute(node_kernel, cudaFuncAttributeMaxDynamicSharedMemorySize, SMEM_BYTES);
    cudaFuncSetAttribute(edge_tc,     cudaFuncAttributeMaxDynamicSharedMemorySize, SMEM_E);

    void *pP, *pT, *pUG;
    cudaGetSymbolAddress(&pP,  g_P);
    cudaGetSymbolAddress(&pT,  g_T);
    cudaGetSymbolAddress(&pUG, g_UG);

    zero_kernel<<<256, 256>>>();
    prep_w<<<128, 256>>>(W1a, W1b);

    // P = x @ W1a[0:128,:] + b1a     [50000, 256]
    gemm_k128<<<(NN + 63) / 64, 256, SMEM_BYTES>>>(x, NN, W1a, b1a, (float*)pP);
    // T = x @ W2a[0:128,:] + b2a     [50000, 256]
    gemm_k128<<<(NN + 63) / 64, 256, SMEM_BYTES>>>(x, NN, W2a, b2a, (float*)pT);
    // UG = u @ W2a[256:384,:]        [64, 256]
    gemm_k128<<<1, 256, SMEM_BYTES>>>(u, NG, W2a + 256 * 256, nullptr, (float*)pUG);

    edge_tc<<<NE / 64, 256, SMEM_E>>>(ea, ei, b1b);

    node_kernel<<<(NN + 63) / 64, 256, SMEM_BYTES>>>(batch, W2a, W2b, b2b, out);
}

// round 12
// speedup vs baseline: 1.8803x; 1.8803x over previous
#include <cuda_runtime.h>
#include <cuda_bf16.h>
#include <cuda_fp16.h>
#include <cstdint>

#define NN 50000
#define NE 800000
#define NG 64

// ---------------- scratch (device globals; no allocation allowed) ----------
__device__ float g_P [NN * 256];   // x @ W1a[0:128,:] + b1a
__device__ float g_T [NN * 256];   // x @ W2a[0:128,:] + b2a
__device__ float g_UG[NG * 256];   // u @ W2a[256:384,:]
__device__ float g_sum[NN * 128];  // scatter-sum of edge MLP output
__device__ int   g_cnt[NN];        // in-degree
// fp16 transposed weights for the tensor-core edge path
__device__ __half g_W1f[256 * 128];  // [n][k] = W1a[128+k][n] (edge_attr half)
__device__ __half g_W2f[128 * 256];  // [n][k] = W1b[k][n]

// ---------------- packed fp32x2 helpers (scalar kernels) --------------------
__device__ __forceinline__ unsigned long long ffma2(unsigned long long a,
                                                    unsigned long long b,
                                                    unsigned long long c) {
    unsigned long long d;
    asm("fma.rn.f32x2 %0, %1, %2, %3;" : "=l"(d) : "l"(a), "l"(b), "l"(c));
    return d;
}
__device__ __forceinline__ unsigned long long dup2(float x) {
    unsigned long long d; unsigned int u = __float_as_uint(x);
    asm("mov.b64 %0, {%1, %1};" : "=l"(d) : "r"(u));
    return d;
}
__device__ __forceinline__ float2 ull2f2(unsigned long long v) {
    float2 f;
    f.x = __uint_as_float((unsigned int)(v & 0xFFFFFFFFULL));
    f.y = __uint_as_float((unsigned int)(v >> 32));
    return f;
}

// ---------------- mma.sync helpers ------------------------------------------
__device__ __forceinline__ uint32_t smem_u32(const void* p) {
    uint32_t a;
    asm("{ .reg .u64 t; cvta.to.shared.u64 t, %1; cvt.u32.u64 %0, t; }"
        : "=r"(a) : "l"(p));
    return a;
}
__device__ __forceinline__ void ldmx4(uint32_t& r0, uint32_t& r1,
                                      uint32_t& r2, uint32_t& r3, uint32_t addr) {
    asm volatile("ldmatrix.sync.aligned.m8n8.x4.shared.b16 {%0,%1,%2,%3}, [%4];"
                 : "=r"(r0), "=r"(r1), "=r"(r2), "=r"(r3) : "r"(addr));
}
__device__ __forceinline__ void mma_f16(float c[4], const uint32_t a[4],
                                        const uint32_t b[2]) {
    asm volatile(
        "mma.sync.aligned.m16n8k16.row.col.f32.f16.f16.f32 "
        "{%0,%1,%2,%3}, {%4,%5,%6,%7}, {%8,%9}, {%0,%1,%2,%3};"
        : "+f"(c[0]), "+f"(c[1]), "+f"(c[2]), "+f"(c[3])
        : "r"(a[0]), "r"(a[1]), "r"(a[2]), "r"(a[3]), "r"(b[0]), "r"(b[1]));
}
// pack float2 -> half2 (x -> low half)
__device__ __forceinline__ uint32_t f2h2(float2 v) {
    uint32_t r;
    asm("cvt.rn.f16x2.f32 %0, %1, %2;" : "=r"(r) : "f"(v.y), "f"(v.x));
    return r;
}
__device__ __forceinline__ float bfr(float v) {
    return __bfloat162float(__float2bfloat16_rn(v));
}

// ---------------- edge kernel smem layout (bytes) ---------------------------
// SM_A : phase1 A fp32 [64][136] = 34816 ; aliased phase2 H fp16 [64][264] = 33792
// SM_B : fp16 [256][40] = 20480 (single buffer, stride 40 halfs = 80 B)
#define SM_A   0
#define SM_B   34816
#define SM_EI  55296
#define SM_CD  55552
#define SM_B1B 55808
#define SMEM_E 56320

// ============================================================================
// fp16 tensor-core edge kernel: 64 edges/CTA, 8 warps (wm = wid&1, wn = wid>>1)
//   C1 = EA @ W1f^T (K=128) ; h = relu(C1 + P[row]) -> sH (fp16, aliases sA)
//   C2 = h @ W2f^T (K=256)  ; scatter-add(C2 + b1b), degree count
// ============================================================================
__global__ __launch_bounds__(256)
void edge_tc(const float* __restrict__ ea,
             const int*   __restrict__ ei,
             const float* __restrict__ b1b) {
    extern __shared__ char sm[];
    float*  sA  = (float*)(sm + SM_A);
    __half* sH  = (__half*)(sm + SM_A);     // aliases sA after phase 1
    int*    sEi = (int*)(sm + SM_EI);
    int*    sCd = (int*)(sm + SM_CD);
    float*  sB1b= (float*)(sm + SM_B1B);
    const uint32_t sbase = smem_u32(sm);
    const uint32_t uB = sbase + SM_B;

    const int tid = threadIdx.x, lane = tid & 31, wid = tid >> 5;
    const int e0 = blockIdx.x * 64;
    const int wm = wid & 1, wn = wid >> 1;
    const int rbase = lane >> 2, cpos = 2 * (lane & 3);

    if (tid < 64) { sEi[tid] = ei[e0 + tid]; sCd[tid] = ei[NE + e0 + tid]; }
    if (tid < 128) sB1b[tid] = b1b[tid];

    // EA tile -> sA fp32 [64][136]
    for (int idx = tid; idx < 2048; idx += 256) {
        int m = idx >> 5, q = idx & 31;
        float4 v = ((const float4*)(ea + (size_t)(e0 + m) * 128))[q];
        *(float4*)(sA + m * 136 + q * 4) = v;
    }

    // ---------------- phase 1: C1[64][256] = EA @ W1f^T ----------------
    float c1[2][8][4];
#pragma unroll
    for (int mt = 0; mt < 2; mt++)
#pragma unroll
        for (int nt = 0; nt < 8; nt++)
#pragma unroll
            for (int q = 0; q < 4; q++) c1[mt][nt][q] = 0.f;

    // ldmatrix lane addressing pieces
    const int g = lane >> 3, r8 = lane & 7;
    const int gk = (g & 1) << 3;          // k offset 0/8
    const int gn = (g >> 1) << 3;         // n offset 0/8

    for (int kc = 0; kc < 4; kc++) {      // K chunks of 32
        __syncthreads();
        {   // stage W1f chunk [256n][32k] (1 row/thread, 64 B)
            const uint4* src = (const uint4*)(g_W1f + tid * 128 + kc * 32);
            uint4* dst = (uint4*)(sm + SM_B + tid * 80);
#pragma unroll
            for (int q = 0; q < 4; q++) dst[q] = src[q];
        }
        __syncthreads();
#pragma unroll
        for (int ks = 0; ks < 2; ks++) {
            const int kg = kc * 32 + ks * 16;
            uint32_t af[2][4];
#pragma unroll
            for (int mt = 0; mt < 2; mt++) {
                const float* base = sA + (wm * 32 + mt * 16 + rbase) * 136 + kg + cpos;
                af[mt][0] = f2h2(*(const float2*)(base));
                af[mt][1] = f2h2(*(const float2*)(base + 8 * 136));
                af[mt][2] = f2h2(*(const float2*)(base + 8));
                af[mt][3] = f2h2(*(const float2*)(base + 8 * 136 + 8));
            }
            uint32_t bf[8][2];
            const uint32_t klb = (uint32_t)(ks * 16 + gk) * 2;
#pragma unroll
            for (int ntp = 0; ntp < 4; ntp++) {
                uint32_t off = (uint32_t)(wn * 64 + ntp * 16 + gn + r8) * 80 + klb;
                ldmx4(bf[2*ntp][0], bf[2*ntp][1], bf[2*ntp+1][0], bf[2*ntp+1][1], uB + off);
            }
#pragma unroll
            for (int mt = 0; mt < 2; mt++)
#pragma unroll
                for (int nt = 0; nt < 8; nt++)
                    mma_f16(c1[mt][nt], af[mt], bf[nt]);
        }
    }
    __syncthreads();   // all phase-1 reads of sA complete before H overwrites it

    // ------- epilogue 1: h = relu(C1 + P[row]) -> sH fp16 [64][264] -------
#pragma unroll
    for (int mt = 0; mt < 2; mt++) {
        int r0 = wm * 32 + mt * 16 + rbase, r1 = r0 + 8;
        const float* P0 = g_P + (size_t)sEi[r0] * 256;
        const float* P1 = g_P + (size_t)sEi[r1] * 256;
#pragma unroll
        for (int nt = 0; nt < 8; nt++) {
            int col = wn * 64 + nt * 8 + cpos;
            float2 q0 = *(const float2*)(P0 + col);
            float2 q1 = *(const float2*)(P1 + col);
            float2 v0, v1;
            v0.x = fmaxf(c1[mt][nt][0] + q0.x, 0.f);
            v0.y = fmaxf(c1[mt][nt][1] + q0.y, 0.f);
            v1.x = fmaxf(c1[mt][nt][2] + q1.x, 0.f);
            v1.y = fmaxf(c1[mt][nt][3] + q1.y, 0.f);
            *(uint32_t*)(sH + r0 * 264 + col) = f2h2(v0);
            *(uint32_t*)(sH + r1 * 264 + col) = f2h2(v1);
        }
    }

    // ---------------- phase 2: C2[64][128] = h @ W2f^T (K=256) ----------------
    float c2[2][4][4];
#pragma unroll
    for (int mt = 0; mt < 2; mt++)
#pragma unroll
        for (int nt = 0; nt < 4; nt++)
#pragma unroll
            for (int q = 0; q < 4; q++) c2[mt][nt][q] = 0.f;

    for (int kc = 0; kc < 8; kc++) {
        __syncthreads();   // H writes visible (first iter); sB reuse safe
        {   // stage W2f chunk [128n][32k] (2 threads/row, 32 B each)
            int rown = tid & 127, half_ = tid >> 7;
            const uint4* src = (const uint4*)(g_W2f + rown * 256 + kc * 32) + half_ * 2;
            uint4* dst = (uint4*)(sm + SM_B + rown * 80) + half_ * 2;
            dst[0] = src[0]; dst[1] = src[1];
        }
        __syncthreads();
#pragma unroll
        for (int ks = 0; ks < 2; ks++) {
            const int kg = kc * 32 + ks * 16;
            uint32_t af[2][4];
#pragma unroll
            for (int mt = 0; mt < 2; mt++) {
                const __half* hb = sH + (wm * 32 + mt * 16 + rbase) * 264 + kg + cpos;
                af[mt][0] = *(const uint32_t*)(hb);
                af[mt][1] = *(const uint32_t*)(hb + 8 * 264);
                af[mt][2] = *(const uint32_t*)(hb + 8);
                af[mt][3] = *(const uint32_t*)(hb + 8 * 264 + 8);
            }
            uint32_t bf[4][2];
            const uint32_t klb = (uint32_t)(ks * 16 + gk) * 2;
#pragma unroll
            for (int ntp = 0; ntp < 2; ntp++) {
                uint32_t off = (uint32_t)(wn * 32 + ntp * 16 + gn + r8) * 80 + klb;
                ldmx4(bf[2*ntp][0], bf[2*ntp][1], bf[2*ntp+1][0], bf[2*ntp+1][1], uB + off);
            }
#pragma unroll
            for (int mt = 0; mt < 2; mt++)
#pragma unroll
                for (int nt = 0; nt < 4; nt++)
                    mma_f16(c2[mt][nt], af[mt], bf[nt]);
        }
    }

    // ---------------- epilogue 2: scatter-add + degree ----------------
#pragma unroll
    for (int mt = 0; mt < 2; mt++) {
        int r0 = wm * 32 + mt * 16 + rbase, r1 = r0 + 8;
        float* s0 = g_sum + (size_t)sCd[r0] * 128;
        float* s1 = g_sum + (size_t)sCd[r1] * 128;
#pragma unroll
        for (int nt = 0; nt < 4; nt++) {
            int col = wn * 32 + nt * 8 + cpos;
            atomicAdd(s0 + col,     c2[mt][nt][0] + sB1b[col]);
            atomicAdd(s0 + col + 1, c2[mt][nt][1] + sB1b[col + 1]);
            atomicAdd(s1 + col,     c2[mt][nt][2] + sB1b[col]);
            atomicAdd(s1 + col + 1, c2[mt][nt][3] + sB1b[col + 1]);
        }
    }
    if (wn == 0 && (lane & 3) == 0) {
#pragma unroll
        for (int q = 0; q < 4; q++)
            atomicAdd(&g_cnt[sCd[wm * 32 + q * 8 + rbase]], 1);
    }
}

// ============================================================================
// prep: transposed fp16 weights
// ============================================================================
__global__ void prep_w(const float* __restrict__ W1a, const float* __restrict__ W1b) {
    int i = blockIdx.x * blockDim.x + threadIdx.x;
    int st = gridDim.x * blockDim.x;
    for (int idx = i; idx < 256 * 128; idx += st) {
        int n = idx >> 7, k = idx & 127;
        g_W1f[idx] = __float2half_rn(W1a[(128 + k) * 256 + n]);
    }
    for (int idx = i; idx < 128 * 256; idx += st) {
        int n = idx >> 8, k = idx & 255;
        g_W2f[idx] = __float2half_rn(W1b[k * 128 + n]);
    }
}

// ---------------- scalar-path shared-memory layout (floats) -----------------
#define SA_STRIDE  132
#define SA_FLOATS  (64 * SA_STRIDE)
#define SWC_OFF    SA_FLOATS
#define SH1_STRIDE 258
#define SH1_FLOATS (64 * SH1_STRIDE)
#define SW2_OFF    SH1_FLOATS
#define SMEM_FLOATS 20736
#define SMEM_BYTES  (SMEM_FLOATS * 4)

__device__ __forceinline__ void p1_chunk(const float* __restrict__ sA,
                                         const float* __restrict__ sWc,
                                         unsigned long long acc[4][8],
                                         int kb, int tx, int ty) {
#pragma unroll 4
    for (int k2 = 0; k2 < 32; k2++) {
        unsigned long long a2[4];
#pragma unroll
        for (int i = 0; i < 4; i++)
            a2[i] = dup2(sA[(ty * 4 + i) * SA_STRIDE + kb + k2]);
        const float* wr = sWc + k2 * 256 + tx * 2;
#pragma unroll
        for (int j = 0; j < 8; j++) {
            unsigned long long w2 = *(const unsigned long long*)(wr + j * 32);
#pragma unroll
            for (int i = 0; i < 4; i++) acc[i][j] = ffma2(a2[i], w2, acc[i][j]);
        }
    }
}

__device__ __forceinline__ void p2_chunk(const float* __restrict__ sH1,
                                         const float* __restrict__ sW2,
                                         unsigned long long acc2[4][4],
                                         int kb, int tx, int ty) {
#pragma unroll 4
    for (int k2 = 0; k2 < 32; k2 += 2) {
        unsigned long long alo[4], ahi[4];
#pragma unroll
        for (int i = 0; i < 4; i++) {
            float2 af = *(const float2*)(sH1 + (ty * 4 + i) * SH1_STRIDE + kb + k2);
            alo[i] = dup2(af.x);
            ahi[i] = dup2(af.y);
        }
#pragma unroll
        for (int j = 0; j < 4; j++) {
            unsigned long long wlo = *(const unsigned long long*)(sW2 + k2 * 128 + j * 32 + tx * 2);
            unsigned long long whi = *(const unsigned long long*)(sW2 + (k2 + 1) * 128 + j * 32 + tx * 2);
#pragma unroll
            for (int i = 0; i < 4; i++) {
                acc2[i][j] = ffma2(alo[i], wlo, acc2[i][j]);
                acc2[i][j] = ffma2(ahi[i], whi, acc2[i][j]);
            }
        }
    }
}

// Pre-GEMM: out[M,256] = A[M,128] @ W[128,256] (+ bias)
__global__ __launch_bounds__(256, 2)
void gemm_k128(const float* __restrict__ A, int M,
               const float* __restrict__ W,
               const float* __restrict__ bias,
               float* __restrict__ out) {
    extern __shared__ float smemf[];
    float* sA  = smemf;
    float* sWc = smemf + SWC_OFF;
    int tid = threadIdx.x;
    int tx = tid & 15, ty = tid >> 4;
    int m0 = blockIdx.x * 64;

    for (int idx = tid; idx < 2048; idx += 256) {
        int m = idx >> 5, kq = idx & 31;
        int gm = m0 + m;
        float4 v = make_float4(0.f, 0.f, 0.f, 0.f);
        if (gm < M) v = ((const float4*)(A + (size_t)gm * 128))[kq];
        *(float4*)(sA + m * SA_STRIDE + kq * 4) = v;
    }

    unsigned long long acc[4][8];
#pragma unroll
    for (int i = 0; i < 4; i++)
#pragma unroll
        for (int j = 0; j < 8; j++) acc[i][j] = 0ULL;

    for (int kb = 0; kb < 128; kb += 32) {
        __syncthreads();
        const float4* wsrc = (const float4*)(W + (size_t)kb * 256);
        for (int idx = tid; idx < 2048; idx += 256)
            ((float4*)sWc)[idx] = wsrc[idx];
        __syncthreads();
        p1_chunk(sA, sWc, acc, kb, tx, ty);
    }

#pragma unroll
    for (int i = 0; i < 4; i++) {
        int gm = m0 + ty * 4 + i;
        if (gm >= M) continue;
        float* orow = out + (size_t)gm * 256;
#pragma unroll
        for (int j = 0; j < 8; j++) {
            int c = j * 32 + tx * 2;
            float2 v = ull2f2(acc[i][j]);
            if (bias) { v.x += bias[c]; v.y += bias[c + 1]; }
            *(float2*)(orow + c) = v;
        }
    }
}

// node kernel: out = relu(agg@W2a_mid + T + UG[batch]) @ W2b + b2b
__global__ __launch_bounds__(256, 2)
void node_kernel(const int* __restrict__ batch,
                 const float* __restrict__ W2a,
                 const float* __restrict__ W2b,
                 const float* __restrict__ b2b,
                 float* __restrict__ out) {
    extern __shared__ float smemf[];
    float* sA  = smemf;
    float* sWc = smemf + SWC_OFF;
    int tid = threadIdx.x;
    int tx = tid & 15, ty = tid >> 4;
    int m0 = blockIdx.x * 64;

    for (int idx = tid; idx < 2048; idx += 256) {
        int m = idx >> 5, kq = idx & 31;
        int gm = m0 + m;
        float4 v = make_float4(0.f, 0.f, 0.f, 0.f);
        if (gm < NN) {
            float sc = 1.0f / fmaxf((float)g_cnt[gm], 1.0f);
            float4 s = ((const float4*)(g_sum + (size_t)gm * 128))[kq];
            v.x = s.x * sc; v.y = s.y * sc; v.z = s.z * sc; v.w = s.w * sc;
        }
        *(float4*)(sA + m * SA_STRIDE + kq * 4) = v;
    }

    unsigned long long acc[4][8];
#pragma unroll
    for (int i = 0; i < 4; i++)
#pragma unroll
        for (int j = 0; j < 8; j++) acc[i][j] = 0ULL;

    const float* Wm = W2a + 128 * 256;
    for (int kb = 0; kb < 128; kb += 32) {
        __syncthreads();
        const float4* wsrc = (const float4*)(Wm + (size_t)kb * 256);
        for (int idx = tid; idx < 2048; idx += 256)
            ((float4*)sWc)[idx] = wsrc[idx];
        __syncthreads();
        p1_chunk(sA, sWc, acc, kb, tx, ty);
    }
    __syncthreads();

    float* sH1 = smemf;
#pragma unroll
    for (int i = 0; i < 4; i++) {
        int gm = m0 + ty * 4 + i;
        float* hrow = sH1 + (ty * 4 + i) * SH1_STRIDE;
        if (gm < NN) {
            const float* Trow = g_T + (size_t)gm * 256;
            const float* Urow = g_UG + (size_t)batch[gm] * 256;
#pragma unroll
            for (int j = 0; j < 8; j++) {
                int c = j * 32 + tx * 2;
                float2 v = ull2f2(acc[i][j]);
                float2 t = *(const float2*)(Trow + c);
                float2 g = *(const float2*)(Urow + c);
                v.x = fmaxf(v.x + t.x + g.x, 0.f);
                v.y = fmaxf(v.y + t.y + g.y, 0.f);
                *(float2*)(hrow + c) = v;
            }
        } else {
#pragma unroll
            for (int j = 0; j < 8; j++) {
                int c = j * 32 + tx * 2;
                *(float2*)(hrow + c) = make_float2(0.f, 0.f);
            }
        }
    }

    float* sW2 = smemf + SW2_OFF;
    unsigned long long acc2[4][4];
#pragma unroll
    for (int i = 0; i < 4; i++)
#pragma unroll
        for (int j = 0; j < 4; j++) acc2[i][j] = 0ULL;

    for (int kb = 0; kb < 256; kb += 32) {
        __syncthreads();
        const float4* wsrc = (const float4*)(W2b + (size_t)kb * 128);
        for (int idx = tid; idx < 1024; idx += 256)
            ((float4*)sW2)[idx] = wsrc[idx];
        __syncthreads();
        p2_chunk(sH1, sW2, acc2, kb, tx, ty);
    }

#pragma unroll
    for (int i = 0; i < 4; i++) {
        int gm = m0 + ty * 4 + i;
        if (gm >= NN) continue;
        float* orow = out + (size_t)gm * 128;
#pragma unroll
        for (int j = 0; j < 4; j++) {
            int c = j * 32 + tx * 2;
            float2 v = ull2f2(acc2[i][j]);
            v.x += b2b[c];
            v.y += b2b[c + 1];
            *(float2*)(orow + c) = v;
        }
    }
}

// ============================================================================
__global__ void zero_kernel() {
    int idx = blockIdx.x * blockDim.x + threadIdx.x;
    int stride = gridDim.x * blockDim.x;
    float4 z = make_float4(0.f, 0.f, 0.f, 0.f);
    for (int i = idx; i < NN * 32; i += stride) ((float4*)g_sum)[i] = z;
    for (int i = idx; i < NN; i += stride) g_cnt[i] = 0;
}

// ============================================================================
extern "C" void kernel_launch(void* const* d_in, const int* in_sizes, int n_in,
                              void* d_out, int out_size) {
    const float* x     = (const float*)d_in[0];
    const int*   ei    = (const int*)d_in[1];     // int32 (JAX x64 disabled)
    const float* ea    = (const float*)d_in[2];
    const float* u     = (const float*)d_in[3];
    const int*   batch = (const int*)d_in[4];
    const float* W1a   = (const float*)d_in[5];
    const float* b1a   = (const float*)d_in[6];
    const float* W1b   = (const float*)d_in[7];
    const float* b1b   = (const float*)d_in[8];
    const float* W2a   = (const float*)d_in[9];
    const float* b2a   = (const float*)d_in[10];
    const float* W2b   = (const float*)d_in[11];
    const float* b2b   = (const float*)d_in[12];
    float* out = (float*)d_out;

    cudaFuncSetAttribute(gemm_k128,   cudaFuncAttributeMaxDynamicSharedMemorySize, SMEM_BYTES);
    cudaFuncSetAttribute(node_kernel, cudaFuncAttributeMaxDynamicSharedMemorySize, SMEM_BYTES);
    cudaFuncSetAttribute(edge_tc,     cudaFuncAttributeMaxDynamicSharedMemorySize, SMEM_E);

    void *pP, *pT, *pUG;
    cudaGetSymbolAddress(&pP,  g_P);
    cudaGetSymbolAddress(&pT,  g_T);
    cudaGetSymbolAddress(&pUG, g_UG);

    zero_kernel<<<256, 256>>>();
    prep_w<<<128, 256>>>(W1a, W1b);

    // P = x @ W1a[0:128,:] + b1a     [50000, 256]
    gemm_k128<<<(NN + 63) / 64, 256, SMEM_BYTES>>>(x, NN, W1a, b1a, (float*)pP);
    // T = x @ W2a[0:128,:] + b2a     [50000, 256]
    gemm_k128<<<(NN + 63) / 64, 256, SMEM_BYTES>>>(x, NN, W2a, b2a, (float*)pT);
    // UG = u @ W2a[256:384,:]        [64, 256]
    gemm_k128<<<1, 256, SMEM_BYTES>>>(u, NG, W2a + 256 * 256, nullptr, (float*)pUG);

    edge_tc<<<NE / 64, 256, SMEM_E>>>(ea, ei, b1b);

    node_kernel<<<(NN + 63) / 64, 256, SMEM_BYTES>>>(batch, W2a, W2b, b2b, out);
}

// round 13
// speedup vs baseline: 2.1881x; 1.1637x over previous
#include <cuda_runtime.h>
#include <cuda_fp16.h>
#include <cstdint>

#define NN 50000
#define NE 800000
#define NG 64

// ---------------- scratch (device globals; no allocation allowed) ----------
__device__ float g_P [NN * 256];   // x @ W1a[0:128,:] + b1a
__device__ float g_T [NN * 256];   // x @ W2a[0:128,:] + b2a
__device__ float g_UG[NG * 256];   // u @ W2a[256:384,:]
__device__ float g_sum[NN * 128];  // scatter-sum of edge MLP output
__device__ int   g_cnt[NN];        // in-degree
// fp16 transposed weights for the tensor-core kernels
__device__ __half g_W1f [256 * 128];  // [n][k] = W1a[128+k][n]  (edge phase1)
__device__ __half g_W2f [128 * 256];  // [n][k] = W1b[k][n]      (edge phase2)
__device__ __half g_W1t [256 * 128];  // [n][k] = W1a[k][n]      (pt phase A)
__device__ __half g_W2t [256 * 128];  // [n][k] = W2a[k][n]      (pt phase B)
__device__ __half g_W2m [256 * 128];  // [n][k] = W2a[128+k][n]  (node phase1)
__device__ __half g_W2bT[128 * 256];  // [n][k] = W2b[k][n]      (node phase2)

// ---------------- packed fp32x2 helpers (scalar UG gemm) --------------------
__device__ __forceinline__ unsigned long long ffma2(unsigned long long a,
                                                    unsigned long long b,
                                                    unsigned long long c) {
    unsigned long long d;
    asm("fma.rn.f32x2 %0, %1, %2, %3;" : "=l"(d) : "l"(a), "l"(b), "l"(c));
    return d;
}
__device__ __forceinline__ unsigned long long dup2(float x) {
    unsigned long long d; unsigned int u = __float_as_uint(x);
    asm("mov.b64 %0, {%1, %1};" : "=l"(d) : "r"(u));
    return d;
}
__device__ __forceinline__ float2 ull2f2(unsigned long long v) {
    float2 f;
    f.x = __uint_as_float((unsigned int)(v & 0xFFFFFFFFULL));
    f.y = __uint_as_float((unsigned int)(v >> 32));
    return f;
}

// ---------------- mma.sync helpers ------------------------------------------
__device__ __forceinline__ uint32_t smem_u32(const void* p) {
    uint32_t a;
    asm("{ .reg .u64 t; cvta.to.shared.u64 t, %1; cvt.u32.u64 %0, t; }"
        : "=r"(a) : "l"(p));
    return a;
}
__device__ __forceinline__ void ldmx4(uint32_t& r0, uint32_t& r1,
                                      uint32_t& r2, uint32_t& r3, uint32_t addr) {
    asm volatile("ldmatrix.sync.aligned.m8n8.x4.shared.b16 {%0,%1,%2,%3}, [%4];"
                 : "=r"(r0), "=r"(r1), "=r"(r2), "=r"(r3) : "r"(addr));
}
__device__ __forceinline__ void mma_f16(float c[4], const uint32_t a[4],
                                        const uint32_t b[2]) {
    asm volatile(
        "mma.sync.aligned.m16n8k16.row.col.f32.f16.f16.f32 "
        "{%0,%1,%2,%3}, {%4,%5,%6,%7}, {%8,%9}, {%0,%1,%2,%3};"
        : "+f"(c[0]), "+f"(c[1]), "+f"(c[2]), "+f"(c[3])
        : "r"(a[0]), "r"(a[1]), "r"(a[2]), "r"(a[3]), "r"(b[0]), "r"(b[1]));
}
// pack float2 -> half2 (x -> low half)
__device__ __forceinline__ uint32_t f2h2(float2 v) {
    uint32_t r;
    asm("cvt.rn.f16x2.f32 %0, %1, %2;" : "=r"(r) : "f"(v.y), "f"(v.x));
    return r;
}

// ---------------- edge kernel smem layout (bytes) ---------------------------
#define SM_A   0        // phase1 A fp32 [64][136]=34816 ; phase2 H fp16 [64][264]=33792
#define SM_B   34816    // fp16 [256][40] = 20480
#define SM_EI  55296
#define SM_CD  55552
#define SM_B1B 55808
#define SMEM_E 56320

// ============================================================================
// fp16 tensor-core edge kernel: 64 edges/CTA, 8 warps (wm = wid&1, wn = wid>>1)
//   C1 = EA @ W1f^T (K=128) ; h = relu(C1 + P[row]) -> sH (fp16, aliases sA)
//   C2 = h @ W2f^T (K=256)  ; scatter-add(C2 + b1b), degree count
// ============================================================================
__global__ __launch_bounds__(256)
void edge_tc(const float* __restrict__ ea,
             const int*   __restrict__ ei,
             const float* __restrict__ b1b) {
    extern __shared__ char sm[];
    float*  sA  = (float*)(sm + SM_A);
    __half* sH  = (__half*)(sm + SM_A);     // aliases sA after phase 1
    int*    sEi = (int*)(sm + SM_EI);
    int*    sCd = (int*)(sm + SM_CD);
    float*  sB1b= (float*)(sm + SM_B1B);
    const uint32_t sbase = smem_u32(sm);
    const uint32_t uB = sbase + SM_B;

    const int tid = threadIdx.x, lane = tid & 31, wid = tid >> 5;
    const int e0 = blockIdx.x * 64;
    const int wm = wid & 1, wn = wid >> 1;
    const int rbase = lane >> 2, cpos = 2 * (lane & 3);

    if (tid < 64) { sEi[tid] = ei[e0 + tid]; sCd[tid] = ei[NE + e0 + tid]; }
    if (tid < 128) sB1b[tid] = b1b[tid];

    // EA tile -> sA fp32 [64][136]
    for (int idx = tid; idx < 2048; idx += 256) {
        int m = idx >> 5, q = idx & 31;
        float4 v = ((const float4*)(ea + (size_t)(e0 + m) * 128))[q];
        *(float4*)(sA + m * 136 + q * 4) = v;
    }

    // ---------------- phase 1: C1[64][256] = EA @ W1f^T ----------------
    float c1[2][8][4];
#pragma unroll
    for (int mt = 0; mt < 2; mt++)
#pragma unroll
        for (int nt = 0; nt < 8; nt++)
#pragma unroll
            for (int q = 0; q < 4; q++) c1[mt][nt][q] = 0.f;

    const int g = lane >> 3, r8 = lane & 7;
    const int gk = (g & 1) << 3;
    const int gn = (g >> 1) << 3;

    for (int kc = 0; kc < 4; kc++) {
        __syncthreads();
        {   // stage W1f chunk [256n][32k] (1 row/thread, 64 B)
            const uint4* src = (const uint4*)(g_W1f + tid * 128 + kc * 32);
            uint4* dst = (uint4*)(sm + SM_B + tid * 80);
#pragma unroll
            for (int q = 0; q < 4; q++) dst[q] = src[q];
        }
        __syncthreads();
#pragma unroll
        for (int ks = 0; ks < 2; ks++) {
            const int kg = kc * 32 + ks * 16;
            uint32_t af[2][4];
#pragma unroll
            for (int mt = 0; mt < 2; mt++) {
                const float* base = sA + (wm * 32 + mt * 16 + rbase) * 136 + kg + cpos;
                af[mt][0] = f2h2(*(const float2*)(base));
                af[mt][1] = f2h2(*(const float2*)(base + 8 * 136));
                af[mt][2] = f2h2(*(const float2*)(base + 8));
                af[mt][3] = f2h2(*(const float2*)(base + 8 * 136 + 8));
            }
            uint32_t bf[8][2];
            const uint32_t klb = (uint32_t)(ks * 16 + gk) * 2;
#pragma unroll
            for (int ntp = 0; ntp < 4; ntp++) {
                uint32_t off = (uint32_t)(wn * 64 + ntp * 16 + gn + r8) * 80 + klb;
                ldmx4(bf[2*ntp][0], bf[2*ntp][1], bf[2*ntp+1][0], bf[2*ntp+1][1], uB + off);
            }
#pragma unroll
            for (int mt = 0; mt < 2; mt++)
#pragma unroll
                for (int nt = 0; nt < 8; nt++)
                    mma_f16(c1[mt][nt], af[mt], bf[nt]);
        }
    }
    __syncthreads();

    // ------- epilogue 1: h = relu(C1 + P[row]) -> sH fp16 [64][264] -------
#pragma unroll
    for (int mt = 0; mt < 2; mt++) {
        int r0 = wm * 32 + mt * 16 + rbase, r1 = r0 + 8;
        const float* P0 = g_P + (size_t)sEi[r0] * 256;
        const float* P1 = g_P + (size_t)sEi[r1] * 256;
#pragma unroll
        for (int nt = 0; nt < 8; nt++) {
            int col = wn * 64 + nt * 8 + cpos;
            float2 q0 = *(const float2*)(P0 + col);
            float2 q1 = *(const float2*)(P1 + col);
            float2 v0, v1;
            v0.x = fmaxf(c1[mt][nt][0] + q0.x, 0.f);
            v0.y = fmaxf(c1[mt][nt][1] + q0.y, 0.f);
            v1.x = fmaxf(c1[mt][nt][2] + q1.x, 0.f);
            v1.y = fmaxf(c1[mt][nt][3] + q1.y, 0.f);
            *(uint32_t*)(sH + r0 * 264 + col) = f2h2(v0);
            *(uint32_t*)(sH + r1 * 264 + col) = f2h2(v1);
        }
    }

    // ---------------- phase 2: C2[64][128] = h @ W2f^T (K=256) ----------------
    float c2[2][4][4];
#pragma unroll
    for (int mt = 0; mt < 2; mt++)
#pragma unroll
        for (int nt = 0; nt < 4; nt++)
#pragma unroll
            for (int q = 0; q < 4; q++) c2[mt][nt][q] = 0.f;

    for (int kc = 0; kc < 8; kc++) {
        __syncthreads();
        {   // stage W2f chunk [128n][32k] (2 threads/row, 32 B each)
            int rown = tid & 127, half_ = tid >> 7;
            const uint4* src = (const uint4*)(g_W2f + rown * 256 + kc * 32) + half_ * 2;
            uint4* dst = (uint4*)(sm + SM_B + rown * 80) + half_ * 2;
            dst[0] = src[0]; dst[1] = src[1];
        }
        __syncthreads();
#pragma unroll
        for (int ks = 0; ks < 2; ks++) {
            const int kg = kc * 32 + ks * 16;
            uint32_t af[2][4];
#pragma unroll
            for (int mt = 0; mt < 2; mt++) {
                const __half* hb = sH + (wm * 32 + mt * 16 + rbase) * 264 + kg + cpos;
                af[mt][0] = *(const uint32_t*)(hb);
                af[mt][1] = *(const uint32_t*)(hb + 8 * 264);
                af[mt][2] = *(const uint32_t*)(hb + 8);
                af[mt][3] = *(const uint32_t*)(hb + 8 * 264 + 8);
            }
            uint32_t bf[4][2];
            const uint32_t klb = (uint32_t)(ks * 16 + gk) * 2;
#pragma unroll
            for (int ntp = 0; ntp < 2; ntp++) {
                uint32_t off = (uint32_t)(wn * 32 + ntp * 16 + gn + r8) * 80 + klb;
                ldmx4(bf[2*ntp][0], bf[2*ntp][1], bf[2*ntp+1][0], bf[2*ntp+1][1], uB + off);
            }
#pragma unroll
            for (int mt = 0; mt < 2; mt++)
#pragma unroll
                for (int nt = 0; nt < 4; nt++)
                    mma_f16(c2[mt][nt], af[mt], bf[nt]);
        }
    }

    // ---------------- epilogue 2: scatter-add + degree ----------------
#pragma unroll
    for (int mt = 0; mt < 2; mt++) {
        int r0 = wm * 32 + mt * 16 + rbase, r1 = r0 + 8;
        float* s0 = g_sum + (size_t)sCd[r0] * 128;
        float* s1 = g_sum + (size_t)sCd[r1] * 128;
#pragma unroll
        for (int nt = 0; nt < 4; nt++) {
            int col = wn * 32 + nt * 8 + cpos;
            atomicAdd(s0 + col,     c2[mt][nt][0] + sB1b[col]);
            atomicAdd(s0 + col + 1, c2[mt][nt][1] + sB1b[col + 1]);
            atomicAdd(s1 + col,     c2[mt][nt][2] + sB1b[col]);
            atomicAdd(s1 + col + 1, c2[mt][nt][3] + sB1b[col + 1]);
        }
    }
    if (wn == 0 && (lane & 3) == 0) {
#pragma unroll
        for (int q = 0; q < 4; q++)
            atomicAdd(&g_cnt[sCd[wm * 32 + q * 8 + rbase]], 1);
    }
}

// ---------------- pt kernel smem layout ---------------------------------
#define SM_PTBA 55296           // biasA floats[256]
#define SM_PTBB 56320           // biasB floats[256]
#define SMEM_PT 57344

// ============================================================================
// pt_tc: per-CTA x-tile [64][128]; two phase-1 passes:
//   P = x @ W1t^T + b1a ;  T = x @ W2t^T + b2a    (both K=128, N=256)
// ============================================================================
__global__ __launch_bounds__(256)
void pt_tc(const float* __restrict__ x,
           const float* __restrict__ b1a,
           const float* __restrict__ b2a) {
    extern __shared__ char sm[];
    float* sA = (float*)(sm + SM_A);
    float* sBa = (float*)(sm + SM_PTBA);
    float* sBb = (float*)(sm + SM_PTBB);
    const uint32_t uB = smem_u32(sm) + SM_B;

    const int tid = threadIdx.x, lane = tid & 31, wid = tid >> 5;
    const int m0 = blockIdx.x * 64;
    const int wm = wid & 1, wn = wid >> 1;
    const int rbase = lane >> 2, cpos = 2 * (lane & 3);
    const int g = lane >> 3, r8 = lane & 7;
    const int gk = (g & 1) << 3, gn = (g >> 1) << 3;

    sBa[tid] = b1a[tid];
    sBb[tid] = b2a[tid];

    // x tile -> sA fp32 [64][136] (guarded)
    for (int idx = tid; idx < 2048; idx += 256) {
        int m = idx >> 5, q = idx & 31;
        int gm = m0 + m;
        float4 v = make_float4(0.f, 0.f, 0.f, 0.f);
        if (gm < NN) v = ((const float4*)(x + (size_t)gm * 128))[q];
        *(float4*)(sA + m * 136 + q * 4) = v;
    }

    for (int ph = 0; ph < 2; ph++) {
        const __half* W = ph ? g_W2t : g_W1t;
        const float* bias = ph ? sBb : sBa;
        float* dst = ph ? g_T : g_P;

        float c1[2][8][4];
#pragma unroll
        for (int mt = 0; mt < 2; mt++)
#pragma unroll
            for (int nt = 0; nt < 8; nt++)
#pragma unroll
                for (int q = 0; q < 4; q++) c1[mt][nt][q] = 0.f;

        for (int kc = 0; kc < 4; kc++) {
            __syncthreads();
            {
                const uint4* src = (const uint4*)(W + tid * 128 + kc * 32);
                uint4* d = (uint4*)(sm + SM_B + tid * 80);
#pragma unroll
                for (int q = 0; q < 4; q++) d[q] = src[q];
            }
            __syncthreads();
#pragma unroll
            for (int ks = 0; ks < 2; ks++) {
                const int kg = kc * 32 + ks * 16;
                uint32_t af[2][4];
#pragma unroll
                for (int mt = 0; mt < 2; mt++) {
                    const float* base = sA + (wm * 32 + mt * 16 + rbase) * 136 + kg + cpos;
                    af[mt][0] = f2h2(*(const float2*)(base));
                    af[mt][1] = f2h2(*(const float2*)(base + 8 * 136));
                    af[mt][2] = f2h2(*(const float2*)(base + 8));
                    af[mt][3] = f2h2(*(const float2*)(base + 8 * 136 + 8));
                }
                uint32_t bf[8][2];
                const uint32_t klb = (uint32_t)(ks * 16 + gk) * 2;
#pragma unroll
                for (int ntp = 0; ntp < 4; ntp++) {
                    uint32_t off = (uint32_t)(wn * 64 + ntp * 16 + gn + r8) * 80 + klb;
                    ldmx4(bf[2*ntp][0], bf[2*ntp][1], bf[2*ntp+1][0], bf[2*ntp+1][1], uB + off);
                }
#pragma unroll
                for (int mt = 0; mt < 2; mt++)
#pragma unroll
                    for (int nt = 0; nt < 8; nt++)
                        mma_f16(c1[mt][nt], af[mt], bf[nt]);
            }
        }
        __syncthreads();   // done with sB before next phase restages

        // epilogue: dst[gm] = c1 + bias
#pragma unroll
        for (int mt = 0; mt < 2; mt++) {
            int r0 = wm * 32 + mt * 16 + rbase, r1 = r0 + 8;
            int gm0 = m0 + r0, gm1 = m0 + r1;
#pragma unroll
            for (int nt = 0; nt < 8; nt++) {
                int col = wn * 64 + nt * 8 + cpos;
                if (gm0 < NN) {
                    float2 v; v.x = c1[mt][nt][0] + bias[col]; v.y = c1[mt][nt][1] + bias[col + 1];
                    *(float2*)(dst + (size_t)gm0 * 256 + col) = v;
                }
                if (gm1 < NN) {
                    float2 v; v.x = c1[mt][nt][2] + bias[col]; v.y = c1[mt][nt][3] + bias[col + 1];
                    *(float2*)(dst + (size_t)gm1 * 256 + col) = v;
                }
            }
        }
    }
}

// ---------------- node kernel smem layout --------------------------------
#define SM_NBATCH 55296        // int[64]
#define SM_NB2B   55552        // float[128]
#define SMEM_N    56064

// ============================================================================
// node_tc: 64 nodes/CTA
//   C1 = agg @ W2m^T (K=128); h = relu(C1 + T[gm] + UG[batch]) -> sH
//   C2 = h @ W2bT^T (K=256) ; out[gm] = C2 + b2b
// ============================================================================
__global__ __launch_bounds__(256)
void node_tc(const int* __restrict__ batch,
             const float* __restrict__ b2b,
             float* __restrict__ out) {
    extern __shared__ char sm[];
    float*  sA  = (float*)(sm + SM_A);
    __half* sH  = (__half*)(sm + SM_A);
    int*    sBt = (int*)(sm + SM_NBATCH);
    float*  sB2b= (float*)(sm + SM_NB2B);
    const uint32_t uB = smem_u32(sm) + SM_B;

    const int tid = threadIdx.x, lane = tid & 31, wid = tid >> 5;
    const int m0 = blockIdx.x * 64;
    const int wm = wid & 1, wn = wid >> 1;
    const int rbase = lane >> 2, cpos = 2 * (lane & 3);
    const int g = lane >> 3, r8 = lane & 7;
    const int gk = (g & 1) << 3, gn = (g >> 1) << 3;

    if (tid < 64) sBt[tid] = (m0 + tid < NN) ? batch[m0 + tid] : 0;
    if (tid < 128) sB2b[tid] = b2b[tid];

    // agg tile -> sA fp32 [64][136]
    for (int idx = tid; idx < 2048; idx += 256) {
        int m = idx >> 5, q = idx & 31;
        int gm = m0 + m;
        float4 v = make_float4(0.f, 0.f, 0.f, 0.f);
        if (gm < NN) {
            float sc = 1.0f / fmaxf((float)g_cnt[gm], 1.0f);
            float4 s = ((const float4*)(g_sum + (size_t)gm * 128))[q];
            v.x = s.x * sc; v.y = s.y * sc; v.z = s.z * sc; v.w = s.w * sc;
        }
        *(float4*)(sA + m * 136 + q * 4) = v;
    }

    // ---------------- phase 1: C1 = agg @ W2m^T ----------------
    float c1[2][8][4];
#pragma unroll
    for (int mt = 0; mt < 2; mt++)
#pragma unroll
        for (int nt = 0; nt < 8; nt++)
#pragma unroll
            for (int q = 0; q < 4; q++) c1[mt][nt][q] = 0.f;

    for (int kc = 0; kc < 4; kc++) {
        __syncthreads();
        {
            const uint4* src = (const uint4*)(g_W2m + tid * 128 + kc * 32);
            uint4* dst = (uint4*)(sm + SM_B + tid * 80);
#pragma unroll
            for (int q = 0; q < 4; q++) dst[q] = src[q];
        }
        __syncthreads();
#pragma unroll
        for (int ks = 0; ks < 2; ks++) {
            const int kg = kc * 32 + ks * 16;
            uint32_t af[2][4];
#pragma unroll
            for (int mt = 0; mt < 2; mt++) {
                const float* base = sA + (wm * 32 + mt * 16 + rbase) * 136 + kg + cpos;
                af[mt][0] = f2h2(*(const float2*)(base));
                af[mt][1] = f2h2(*(const float2*)(base + 8 * 136));
                af[mt][2] = f2h2(*(const float2*)(base + 8));
                af[mt][3] = f2h2(*(const float2*)(base + 8 * 136 + 8));
            }
            uint32_t bf[8][2];
            const uint32_t klb = (uint32_t)(ks * 16 + gk) * 2;
#pragma unroll
            for (int ntp = 0; ntp < 4; ntp++) {
                uint32_t off = (uint32_t)(wn * 64 + ntp * 16 + gn + r8) * 80 + klb;
                ldmx4(bf[2*ntp][0], bf[2*ntp][1], bf[2*ntp+1][0], bf[2*ntp+1][1], uB + off);
            }
#pragma unroll
            for (int mt = 0; mt < 2; mt++)
#pragma unroll
                for (int nt = 0; nt < 8; nt++)
                    mma_f16(c1[mt][nt], af[mt], bf[nt]);
        }
    }
    __syncthreads();

    // ------- epilogue 1: h = relu(C1 + T + UG[batch]) -> sH fp16 -------
#pragma unroll
    for (int mt = 0; mt < 2; mt++) {
        int r0 = wm * 32 + mt * 16 + rbase, r1 = r0 + 8;
        int gm0 = m0 + r0, gm1 = m0 + r1;
        const float* T0 = g_T + (size_t)gm0 * 256;
        const float* T1 = g_T + (size_t)gm1 * 256;
        const float* U0 = g_UG + (size_t)sBt[r0] * 256;
        const float* U1 = g_UG + (size_t)sBt[r1] * 256;
#pragma unroll
        for (int nt = 0; nt < 8; nt++) {
            int col = wn * 64 + nt * 8 + cpos;
            float2 v0 = make_float2(0.f, 0.f), v1 = make_float2(0.f, 0.f);
            if (gm0 < NN) {
                float2 t = *(const float2*)(T0 + col);
                float2 ug = *(const float2*)(U0 + col);
                v0.x = fmaxf(c1[mt][nt][0] + t.x + ug.x, 0.f);
                v0.y = fmaxf(c1[mt][nt][1] + t.y + ug.y, 0.f);
            }
            if (gm1 < NN) {
                float2 t = *(const float2*)(T1 + col);
                float2 ug = *(const float2*)(U1 + col);
                v1.x = fmaxf(c1[mt][nt][2] + t.x + ug.x, 0.f);
                v1.y = fmaxf(c1[mt][nt][3] + t.y + ug.y, 0.f);
            }
            *(uint32_t*)(sH + r0 * 264 + col) = f2h2(v0);
            *(uint32_t*)(sH + r1 * 264 + col) = f2h2(v1);
        }
    }

    // ---------------- phase 2: C2 = h @ W2bT^T (K=256) ----------------
    float c2[2][4][4];
#pragma unroll
    for (int mt = 0; mt < 2; mt++)
#pragma unroll
        for (int nt = 0; nt < 4; nt++)
#pragma unroll
            for (int q = 0; q < 4; q++) c2[mt][nt][q] = 0.f;

    for (int kc = 0; kc < 8; kc++) {
        __syncthreads();
        {
            int rown = tid & 127, half_ = tid >> 7;
            const uint4* src = (const uint4*)(g_W2bT + rown * 256 + kc * 32) + half_ * 2;
            uint4* dst = (uint4*)(sm + SM_B + rown * 80) + half_ * 2;
            dst[0] = src[0]; dst[1] = src[1];
        }
        __syncthreads();
#pragma unroll
        for (int ks = 0; ks < 2; ks++) {
            const int kg = kc * 32 + ks * 16;
            uint32_t af[2][4];
#pragma unroll
            for (int mt = 0; mt < 2; mt++) {
                const __half* hb = sH + (wm * 32 + mt * 16 + rbase) * 264 + kg + cpos;
                af[mt][0] = *(const uint32_t*)(hb);
                af[mt][1] = *(const uint32_t*)(hb + 8 * 264);
                af[mt][2] = *(const uint32_t*)(hb + 8);
                af[mt][3] = *(const uint32_t*)(hb + 8 * 264 + 8);
            }
            uint32_t bf[4][2];
            const uint32_t klb = (uint32_t)(ks * 16 + gk) * 2;
#pragma unroll
            for (int ntp = 0; ntp < 2; ntp++) {
                uint32_t off = (uint32_t)(wn * 32 + ntp * 16 + gn + r8) * 80 + klb;
                ldmx4(bf[2*ntp][0], bf[2*ntp][1], bf[2*ntp+1][0], bf[2*ntp+1][1], uB + off);
            }
#pragma unroll
            for (int mt = 0; mt < 2; mt++)
#pragma unroll
                for (int nt = 0; nt < 4; nt++)
                    mma_f16(c2[mt][nt], af[mt], bf[nt]);
        }
    }

    // ---------------- epilogue 2: out = C2 + b2b ----------------
#pragma unroll
    for (int mt = 0; mt < 2; mt++) {
        int r0 = wm * 32 + mt * 16 + rbase, r1 = r0 + 8;
        int gm0 = m0 + r0, gm1 = m0 + r1;
#pragma unroll
        for (int nt = 0; nt < 4; nt++) {
            int col = wn * 32 + nt * 8 + cpos;
            if (gm0 < NN) {
                float2 v; v.x = c2[mt][nt][0] + sB2b[col]; v.y = c2[mt][nt][1] + sB2b[col + 1];
                *(float2*)(out + (size_t)gm0 * 128 + col) = v;
            }
            if (gm1 < NN) {
                float2 v; v.x = c2[mt][nt][2] + sB2b[col]; v.y = c2[mt][nt][3] + sB2b[col + 1];
                *(float2*)(out + (size_t)gm1 * 128 + col) = v;
            }
        }
    }
}

// ============================================================================
// prep: transposed fp16 weights
// ============================================================================
__global__ void prep_w(const float* __restrict__ W1a, const float* __restrict__ W1b,
                       const float* __restrict__ W2a, const float* __restrict__ W2b) {
    int i = blockIdx.x * blockDim.x + threadIdx.x;
    int st = gridDim.x * blockDim.x;
    for (int idx = i; idx < 256 * 128; idx += st) {
        int n = idx >> 7, k = idx & 127;
        g_W1f[idx] = __float2half_rn(W1a[(128 + k) * 256 + n]);
        g_W1t[idx] = __float2half_rn(W1a[k * 256 + n]);
        g_W2t[idx] = __float2half_rn(W2a[k * 256 + n]);
        g_W2m[idx] = __float2half_rn(W2a[(128 + k) * 256 + n]);
    }
    for (int idx = i; idx < 128 * 256; idx += st) {
        int n = idx >> 8, k = idx & 255;
        g_W2f[idx]  = __float2half_rn(W1b[k * 128 + n]);
        g_W2bT[idx] = __float2half_rn(W2b[k * 128 + n]);
    }
}

// ---------------- scalar UG gemm (grid=1 only) ------------------------------
#define SA_STRIDE  132
#define SA_FLOATS  (64 * SA_STRIDE)
#define SWC_OFF    SA_FLOATS
#define SMEM_FLOATS (SWC_OFF + 32 * 256)
#define SMEM_BYTES  (SMEM_FLOATS * 4)

__device__ __forceinline__ void p1_chunk(const float* __restrict__ sA,
                                         const float* __restrict__ sWc,
                                         unsigned long long acc[4][8],
                                         int kb, int tx, int ty) {
#pragma unroll 4
    for (int k2 = 0; k2 < 32; k2++) {
        unsigned long long a2[4];
#pragma unroll
        for (int i = 0; i < 4; i++)
            a2[i] = dup2(sA[(ty * 4 + i) * SA_STRIDE + kb + k2]);
        const float* wr = sWc + k2 * 256 + tx * 2;
#pragma unroll
        for (int j = 0; j < 8; j++) {
            unsigned long long w2 = *(const unsigned long long*)(wr + j * 32);
#pragma unroll
            for (int i = 0; i < 4; i++) acc[i][j] = ffma2(a2[i], w2, acc[i][j]);
        }
    }
}

__global__ __launch_bounds__(256, 2)
void gemm_k128(const float* __restrict__ A, int M,
               const float* __restrict__ W,
               const float* __restrict__ bias,
               float* __restrict__ out) {
    extern __shared__ float smemf[];
    float* sA  = smemf;
    float* sWc = smemf + SWC_OFF;
    int tid = threadIdx.x;
    int tx = tid & 15, ty = tid >> 4;
    int m0 = blockIdx.x * 64;

    for (int idx = tid; idx < 2048; idx += 256) {
        int m = idx >> 5, kq = idx & 31;
        int gm = m0 + m;
        float4 v = make_float4(0.f, 0.f, 0.f, 0.f);
        if (gm < M) v = ((const float4*)(A + (size_t)gm * 128))[kq];
        *(float4*)(sA + m * SA_STRIDE + kq * 4) = v;
    }

    unsigned long long acc[4][8];
#pragma unroll
    for (int i = 0; i < 4; i++)
#pragma unroll
        for (int j = 0; j < 8; j++) acc[i][j] = 0ULL;

    for (int kb = 0; kb < 128; kb += 32) {
        __syncthreads();
        const float4* wsrc = (const float4*)(W + (size_t)kb * 256);
        for (int idx = tid; idx < 2048; idx += 256)
            ((float4*)sWc)[idx] = wsrc[idx];
        __syncthreads();
        p1_chunk(sA, sWc, acc, kb, tx, ty);
    }

#pragma unroll
    for (int i = 0; i < 4; i++) {
        int gm = m0 + ty * 4 + i;
        if (gm >= M) continue;
        float* orow = out + (size_t)gm * 256;
#pragma unroll
        for (int j = 0; j < 8; j++) {
            int c = j * 32 + tx * 2;
            float2 v = ull2f2(acc[i][j]);
            if (bias) { v.x += bias[c]; v.y += bias[c + 1]; }
            *(float2*)(orow + c) = v;
        }
    }
}

// ============================================================================
__global__ void zero_kernel() {
    int idx = blockIdx.x * blockDim.x + threadIdx.x;
    int stride = gridDim.x * blockDim.x;
    float4 z = make_float4(0.f, 0.f, 0.f, 0.f);
    for (int i = idx; i < NN * 32; i += stride) ((float4*)g_sum)[i] = z;
    for (int i = idx; i < NN; i += stride) g_cnt[i] = 0;
}

// ============================================================================
extern "C" void kernel_launch(void* const* d_in, const int* in_sizes, int n_in,
                              void* d_out, int out_size) {
    const float* x     = (const float*)d_in[0];
    const int*   ei    = (const int*)d_in[1];     // int32 (JAX x64 disabled)
    const float* ea    = (const float*)d_in[2];
    const float* u     = (const float*)d_in[3];
    const int*   batch = (const int*)d_in[4];
    const float* W1a   = (const float*)d_in[5];
    const float* b1a   = (const float*)d_in[6];
    const float* W1b   = (const float*)d_in[7];
    const float* b1b   = (const float*)d_in[8];
    const float* W2a   = (const float*)d_in[9];
    const float* b2a   = (const float*)d_in[10];
    const float* W2b   = (const float*)d_in[11];
    const float* b2b   = (const float*)d_in[12];
    float* out = (float*)d_out;

    cudaFuncSetAttribute(gemm_k128, cudaFuncAttributeMaxDynamicSharedMemorySize, SMEM_BYTES);
    cudaFuncSetAttribute(edge_tc,   cudaFuncAttributeMaxDynamicSharedMemorySize, SMEM_E);
    cudaFuncSetAttribute(pt_tc,     cudaFuncAttributeMaxDynamicSharedMemorySize, SMEM_PT);
    cudaFuncSetAttribute(node_tc,   cudaFuncAttributeMaxDynamicSharedMemorySize, SMEM_N);

    void* pUG;
    cudaGetSymbolAddress(&pUG, g_UG);

    zero_kernel<<<256, 256>>>();
    prep_w<<<128, 256>>>(W1a, W1b, W2a, W2b);

    // P = x@W1a_top + b1a ; T = x@W2a_top + b2a    (fp16 mma)
    pt_tc<<<(NN + 63) / 64, 256, SMEM_PT>>>(x, b1a, b2a);
    // UG = u @ W2a[256:384,:]   (scalar, grid=1)
    gemm_k128<<<1, 256, SMEM_BYTES>>>(u, NG, W2a + 256 * 256, nullptr, (float*)pUG);

    edge_tc<<<NE / 64, 256, SMEM_E>>>(ea, ei, b1b);

    node_tc<<<(NN + 63) / 64, 256, SMEM_N>>>(batch, b2b, out);
}

// round 14
// speedup vs baseline: 3.4829x; 1.5917x over previous
#include <cuda_runtime.h>
#include <cuda_fp16.h>
#include <cstdint>

#define NN 50000
#define NE 800000
#define NG 64

// ---------------- scratch (device globals; no allocation allowed) ----------
__device__ float g_P [NN * 256];   // x @ W1a[0:128,:] + b1a
__device__ float g_T [NN * 256];   // x @ W2a[0:128,:] + b2a
__device__ float g_UG[NG * 256];   // u @ W2a[256:384,:]
__device__ float g_sum[NN * 128];  // scatter-sum of edge MLP output
__device__ int   g_cnt[NN];        // in-degree
// fp16 transposed weights for the tensor-core kernels
__device__ __half g_W1f [256 * 128];  // [n][k] = W1a[128+k][n]  (edge phase1)
__device__ __half g_W2f [128 * 256];  // [n][k] = W1b[k][n]      (edge phase2)
__device__ __half g_W1t [256 * 128];  // [n][k] = W1a[k][n]      (pt phase A)
__device__ __half g_W2t [256 * 128];  // [n][k] = W2a[k][n]      (pt phase B)
__device__ __half g_W2m [256 * 128];  // [n][k] = W2a[128+k][n]  (node phase1)
__device__ __half g_W2bT[128 * 256];  // [n][k] = W2b[k][n]      (node phase2)

// ---------------- packed fp32x2 helpers (scalar UG gemm) --------------------
__device__ __forceinline__ unsigned long long ffma2(unsigned long long a,
                                                    unsigned long long b,
                                                    unsigned long long c) {
    unsigned long long d;
    asm("fma.rn.f32x2 %0, %1, %2, %3;" : "=l"(d) : "l"(a), "l"(b), "l"(c));
    return d;
}
__device__ __forceinline__ unsigned long long dup2(float x) {
    unsigned long long d; unsigned int u = __float_as_uint(x);
    asm("mov.b64 %0, {%1, %1};" : "=l"(d) : "r"(u));
    return d;
}
__device__ __forceinline__ float2 ull2f2(unsigned long long v) {
    float2 f;
    f.x = __uint_as_float((unsigned int)(v & 0xFFFFFFFFULL));
    f.y = __uint_as_float((unsigned int)(v >> 32));
    return f;
}

// ---------------- mma.sync helpers ------------------------------------------
__device__ __forceinline__ uint32_t smem_u32(const void* p) {
    uint32_t a;
    asm("{ .reg .u64 t; cvta.to.shared.u64 t, %1; cvt.u32.u64 %0, t; }"
        : "=r"(a) : "l"(p));
    return a;
}
__device__ __forceinline__ void ldmx4(uint32_t& r0, uint32_t& r1,
                                      uint32_t& r2, uint32_t& r3, uint32_t addr) {
    asm volatile("ldmatrix.sync.aligned.m8n8.x4.shared.b16 {%0,%1,%2,%3}, [%4];"
                 : "=r"(r0), "=r"(r1), "=r"(r2), "=r"(r3) : "r"(addr));
}
__device__ __forceinline__ void mma_f16(float c[4], const uint32_t a[4],
                                        const uint32_t b[2]) {
    asm volatile(
        "mma.sync.aligned.m16n8k16.row.col.f32.f16.f16.f32 "
        "{%0,%1,%2,%3}, {%4,%5,%6,%7}, {%8,%9}, {%0,%1,%2,%3};"
        : "+f"(c[0]), "+f"(c[1]), "+f"(c[2]), "+f"(c[3])
        : "r"(a[0]), "r"(a[1]), "r"(a[2]), "r"(a[3]), "r"(b[0]), "r"(b[1]));
}
// pack float2 -> half2 (x -> low half)
__device__ __forceinline__ uint32_t f2h2(float2 v) {
    uint32_t r;
    asm("cvt.rn.f16x2.f32 %0, %1, %2;" : "=r"(r) : "f"(v.y), "f"(v.x));
    return r;
}

// ============================================================================
// Persistent edge kernel smem layout (bytes):
//   SM_AH : A fp16 [128][136] = 34816 ; aliased H fp16 [128][264] = 67584
//   SM_W1 : W1f fp16 [256][136] = 69632  (persistent, ldmatrix-padded)
//   SM_W2 : W2f fp16 [128][264] = 67584  (persistent)
// ============================================================================
#define SM_AH  0
#define SM_W1  67584
#define SM_W2  137216
#define SM_EI  204800
#define SM_CD  205312
#define SM_B1B 205824
#define SMEM_E 206336
#define NTILES (NE / 128)     // 6250
#define EDGE_GRID 152

// ============================================================================
// edge_tc: persistent CTAs, 512 threads (16 warps: wm = wid&3, wn = wid>>2),
// 128 edges/tile. Weights resident in smem for the whole kernel.
//   C1 = EA @ W1f^T (K=128) ; h = relu(C1 + P[row]) -> H (fp16, aliases A)
//   C2 = h @ W2f^T (K=256)  ; scatter-add(C2 + b1b), degree count
// ============================================================================
__global__ __launch_bounds__(512, 1)
void edge_tc(const float* __restrict__ ea,
             const int*   __restrict__ ei,
             const float* __restrict__ b1b) {
    extern __shared__ char sm[];
    __half* sAH = (__half*)(sm + SM_AH);
    int*    sEi = (int*)(sm + SM_EI);
    int*    sCd = (int*)(sm + SM_CD);
    float*  sB1b= (float*)(sm + SM_B1B);
    const uint32_t sbase = smem_u32(sm);
    const uint32_t uW1 = sbase + SM_W1, uW2 = sbase + SM_W2;

    const int tid = threadIdx.x, lane = tid & 31, wid = tid >> 5;
    const int wm = wid & 3, wn = wid >> 2;
    const int rbase = lane >> 2, cpos = 2 * (lane & 3);
    const int g = lane >> 3, r8 = lane & 7;
    const int gk = (g & 1) << 3, gn = (g >> 1) << 3;

    // ---- stage weights once (padded strides: W1 136 halfs, W2 264 halfs) ----
    for (int c = tid; c < 4096; c += 512) {
        int row = c >> 4, kp = (c & 15) * 8;
        *(uint4*)(sm + SM_W1 + row * 272 + kp * 2) =
            *(const uint4*)(g_W1f + row * 128 + kp);
    }
    for (int c = tid; c < 4096; c += 512) {
        int row = c >> 5, kp = (c & 31) * 8;
        *(uint4*)(sm + SM_W2 + row * 528 + kp * 2) =
            *(const uint4*)(g_W2f + row * 256 + kp);
    }
    if (tid < 128) sB1b[tid] = b1b[tid];

    for (int tile = blockIdx.x; tile < NTILES; tile += gridDim.x) {
        const int e0 = tile * 128;
        if (tid < 128) { sEi[tid] = ei[e0 + tid]; sCd[tid] = ei[NE + e0 + tid]; }

        // A tile load: fp32 -> fp16, stride 136 halfs
        for (int idx = tid; idx < 4096; idx += 512) {
            int m = idx >> 5, q = idx & 31;
            float4 v = ((const float4*)(ea + (size_t)(e0 + m) * 128))[q];
            uint32_t h0 = f2h2(make_float2(v.x, v.y));
            uint32_t h1 = f2h2(make_float2(v.z, v.w));
            *(uint2*)(sm + SM_AH + (m * 136 + q * 4) * 2) = make_uint2(h0, h1);
        }
        __syncthreads();   // A + indices ready; weights ready (1st iter too)

        // ---------------- phase 1: C1[128][256] = A @ W1f^T (K=128) ---------
        float c1[2][8][4];
#pragma unroll
        for (int mt = 0; mt < 2; mt++)
#pragma unroll
            for (int nt = 0; nt < 8; nt++)
#pragma unroll
                for (int q = 0; q < 4; q++) c1[mt][nt][q] = 0.f;

#pragma unroll 2
        for (int kc = 0; kc < 8; kc++) {
            const int kg = kc * 16;
            uint32_t af[2][4];
#pragma unroll
            for (int mt = 0; mt < 2; mt++) {
                const __half* hb = sAH + (wm * 32 + mt * 16 + rbase) * 136 + kg + cpos;
                af[mt][0] = *(const uint32_t*)(hb);
                af[mt][1] = *(const uint32_t*)(hb + 8 * 136);
                af[mt][2] = *(const uint32_t*)(hb + 8);
                af[mt][3] = *(const uint32_t*)(hb + 8 * 136 + 8);
            }
            uint32_t bf[8][2];
#pragma unroll
            for (int ntp = 0; ntp < 4; ntp++) {
                uint32_t off = (uint32_t)(wn * 64 + ntp * 16 + gn + r8) * 272
                             + (uint32_t)(kg + gk) * 2;
                ldmx4(bf[2*ntp][0], bf[2*ntp][1], bf[2*ntp+1][0], bf[2*ntp+1][1], uW1 + off);
            }
#pragma unroll
            for (int mt = 0; mt < 2; mt++)
#pragma unroll
                for (int nt = 0; nt < 8; nt++)
                    mma_f16(c1[mt][nt], af[mt], bf[nt]);
        }
        __syncthreads();   // phase-1 reads of A done before H overwrites

        // ------- epilogue 1: h = relu(C1 + P[row]) -> H fp16 [128][264] -----
#pragma unroll
        for (int mt = 0; mt < 2; mt++) {
            int r0 = wm * 32 + mt * 16 + rbase, r1 = r0 + 8;
            const float* P0 = g_P + (size_t)sEi[r0] * 256;
            const float* P1 = g_P + (size_t)sEi[r1] * 256;
#pragma unroll
            for (int nt = 0; nt < 8; nt++) {
                int col = wn * 64 + nt * 8 + cpos;
                float2 q0 = *(const float2*)(P0 + col);
                float2 q1 = *(const float2*)(P1 + col);
                float2 v0, v1;
                v0.x = fmaxf(c1[mt][nt][0] + q0.x, 0.f);
                v0.y = fmaxf(c1[mt][nt][1] + q0.y, 0.f);
                v1.x = fmaxf(c1[mt][nt][2] + q1.x, 0.f);
                v1.y = fmaxf(c1[mt][nt][3] + q1.y, 0.f);
                *(uint32_t*)(sAH + r0 * 264 + col) = f2h2(v0);
                *(uint32_t*)(sAH + r1 * 264 + col) = f2h2(v1);
            }
        }
        __syncthreads();   // H fully written before phase 2 reads

        // ---------------- phase 2: C2[128][128] = H @ W2f^T (K=256) ---------
        float c2[2][4][4];
#pragma unroll
        for (int mt = 0; mt < 2; mt++)
#pragma unroll
            for (int nt = 0; nt < 4; nt++)
#pragma unroll
                for (int q = 0; q < 4; q++) c2[mt][nt][q] = 0.f;

#pragma unroll 2
        for (int kc = 0; kc < 16; kc++) {
            const int kg = kc * 16;
            uint32_t af[2][4];
#pragma unroll
            for (int mt = 0; mt < 2; mt++) {
                const __half* hb = sAH + (wm * 32 + mt * 16 + rbase) * 264 + kg + cpos;
                af[mt][0] = *(const uint32_t*)(hb);
                af[mt][1] = *(const uint32_t*)(hb + 8 * 264);
                af[mt][2] = *(const uint32_t*)(hb + 8);
                af[mt][3] = *(const uint32_t*)(hb + 8 * 264 + 8);
            }
            uint32_t bf[4][2];
#pragma unroll
            for (int ntp = 0; ntp < 2; ntp++) {
                uint32_t off = (uint32_t)(wn * 32 + ntp * 16 + gn + r8) * 528
                             + (uint32_t)(kg + gk) * 2;
                ldmx4(bf[2*ntp][0], bf[2*ntp][1], bf[2*ntp+1][0], bf[2*ntp+1][1], uW2 + off);
            }
#pragma unroll
            for (int mt = 0; mt < 2; mt++)
#pragma unroll
                for (int nt = 0; nt < 4; nt++)
                    mma_f16(c2[mt][nt], af[mt], bf[nt]);
        }

        // ---------------- epilogue 2: scatter-add + degree ----------------
#pragma unroll
        for (int mt = 0; mt < 2; mt++) {
            int r0 = wm * 32 + mt * 16 + rbase, r1 = r0 + 8;
            float* s0 = g_sum + (size_t)sCd[r0] * 128;
            float* s1 = g_sum + (size_t)sCd[r1] * 128;
#pragma unroll
            for (int nt = 0; nt < 4; nt++) {
                int col = wn * 32 + nt * 8 + cpos;
                atomicAdd(s0 + col,     c2[mt][nt][0] + sB1b[col]);
                atomicAdd(s0 + col + 1, c2[mt][nt][1] + sB1b[col + 1]);
                atomicAdd(s1 + col,     c2[mt][nt][2] + sB1b[col]);
                atomicAdd(s1 + col + 1, c2[mt][nt][3] + sB1b[col + 1]);
            }
        }
        if (wn == 0 && (lane & 3) == 0) {
#pragma unroll
            for (int q = 0; q < 4; q++)
                atomicAdd(&g_cnt[sCd[wm * 32 + q * 8 + rbase]], 1);
        }
        __syncthreads();   // phase-2/epi reads done before next tile's A load
    }
}

// ---------------- pt/node kernels: 64-row tiles, 256 threads ----------------
#define SM_A   0        // A fp32 [64][136]=34816 ; H fp16 [64][264]=33792
#define SM_B   34816    // fp16 [256][40] = 20480
#define SM_PTBA 55296
#define SM_PTBB 56320
#define SMEM_PT 57344

// ============================================================================
// pt_tc: per-CTA x-tile [64][128]; two phase-1 passes:
//   P = x @ W1t^T + b1a ;  T = x @ W2t^T + b2a    (both K=128, N=256)
// ============================================================================
__global__ __launch_bounds__(256)
void pt_tc(const float* __restrict__ x,
           const float* __restrict__ b1a,
           const float* __restrict__ b2a) {
    extern __shared__ char sm[];
    float* sA = (float*)(sm + SM_A);
    float* sBa = (float*)(sm + SM_PTBA);
    float* sBb = (float*)(sm + SM_PTBB);
    const uint32_t uB = smem_u32(sm) + SM_B;

    const int tid = threadIdx.x, lane = tid & 31, wid = tid >> 5;
    const int m0 = blockIdx.x * 64;
    const int wm = wid & 1, wn = wid >> 1;
    const int rbase = lane >> 2, cpos = 2 * (lane & 3);
    const int g = lane >> 3, r8 = lane & 7;
    const int gk = (g & 1) << 3, gn = (g >> 1) << 3;

    sBa[tid] = b1a[tid];
    sBb[tid] = b2a[tid];

    for (int idx = tid; idx < 2048; idx += 256) {
        int m = idx >> 5, q = idx & 31;
        int gm = m0 + m;
        float4 v = make_float4(0.f, 0.f, 0.f, 0.f);
        if (gm < NN) v = ((const float4*)(x + (size_t)gm * 128))[q];
        *(float4*)(sA + m * 136 + q * 4) = v;
    }

    for (int ph = 0; ph < 2; ph++) {
        const __half* W = ph ? g_W2t : g_W1t;
        const float* bias = ph ? sBb : sBa;
        float* dst = ph ? g_T : g_P;

        float c1[2][8][4];
#pragma unroll
        for (int mt = 0; mt < 2; mt++)
#pragma unroll
            for (int nt = 0; nt < 8; nt++)
#pragma unroll
                for (int q = 0; q < 4; q++) c1[mt][nt][q] = 0.f;

        for (int kc = 0; kc < 4; kc++) {
            __syncthreads();
            {
                const uint4* src = (const uint4*)(W + tid * 128 + kc * 32);
                uint4* d = (uint4*)(sm + SM_B + tid * 80);
#pragma unroll
                for (int q = 0; q < 4; q++) d[q] = src[q];
            }
            __syncthreads();
#pragma unroll
            for (int ks = 0; ks < 2; ks++) {
                const int kg = kc * 32 + ks * 16;
                uint32_t af[2][4];
#pragma unroll
                for (int mt = 0; mt < 2; mt++) {
                    const float* base = sA + (wm * 32 + mt * 16 + rbase) * 136 + kg + cpos;
                    af[mt][0] = f2h2(*(const float2*)(base));
                    af[mt][1] = f2h2(*(const float2*)(base + 8 * 136));
                    af[mt][2] = f2h2(*(const float2*)(base + 8));
                    af[mt][3] = f2h2(*(const float2*)(base + 8 * 136 + 8));
                }
                uint32_t bf[8][2];
                const uint32_t klb = (uint32_t)(ks * 16 + gk) * 2;
#pragma unroll
                for (int ntp = 0; ntp < 4; ntp++) {
                    uint32_t off = (uint32_t)(wn * 64 + ntp * 16 + gn + r8) * 80 + klb;
                    ldmx4(bf[2*ntp][0], bf[2*ntp][1], bf[2*ntp+1][0], bf[2*ntp+1][1], uB + off);
                }
#pragma unroll
                for (int mt = 0; mt < 2; mt++)
#pragma unroll
                    for (int nt = 0; nt < 8; nt++)
                        mma_f16(c1[mt][nt], af[mt], bf[nt]);
            }
        }
        __syncthreads();

#pragma unroll
        for (int mt = 0; mt < 2; mt++) {
            int r0 = wm * 32 + mt * 16 + rbase, r1 = r0 + 8;
            int gm0 = m0 + r0, gm1 = m0 + r1;
#pragma unroll
            for (int nt = 0; nt < 8; nt++) {
                int col = wn * 64 + nt * 8 + cpos;
                if (gm0 < NN) {
                    float2 v; v.x = c1[mt][nt][0] + bias[col]; v.y = c1[mt][nt][1] + bias[col + 1];
                    *(float2*)(dst + (size_t)gm0 * 256 + col) = v;
                }
                if (gm1 < NN) {
                    float2 v; v.x = c1[mt][nt][2] + bias[col]; v.y = c1[mt][nt][3] + bias[col + 1];
                    *(float2*)(dst + (size_t)gm1 * 256 + col) = v;
                }
            }
        }
    }
}

// ---------------- node kernel smem layout --------------------------------
#define SM_NBATCH 55296
#define SM_NB2B   55552
#define SMEM_N    56064

// ============================================================================
// node_tc: 64 nodes/CTA
//   C1 = agg @ W2m^T (K=128); h = relu(C1 + T[gm] + UG[batch]) -> sH
//   C2 = h @ W2bT^T (K=256) ; out[gm] = C2 + b2b
// ============================================================================
__global__ __launch_bounds__(256)
void node_tc(const int* __restrict__ batch,
             const float* __restrict__ b2b,
             float* __restrict__ out) {
    extern __shared__ char sm[];
    float*  sA  = (float*)(sm + SM_A);
    __half* sH  = (__half*)(sm + SM_A);
    int*    sBt = (int*)(sm + SM_NBATCH);
    float*  sB2b= (float*)(sm + SM_NB2B);
    const uint32_t uB = smem_u32(sm) + SM_B;

    const int tid = threadIdx.x, lane = tid & 31, wid = tid >> 5;
    const int m0 = blockIdx.x * 64;
    const int wm = wid & 1, wn = wid >> 1;
    const int rbase = lane >> 2, cpos = 2 * (lane & 3);
    const int g = lane >> 3, r8 = lane & 7;
    const int gk = (g & 1) << 3, gn = (g >> 1) << 3;

    if (tid < 64) sBt[tid] = (m0 + tid < NN) ? batch[m0 + tid] : 0;
    if (tid < 128) sB2b[tid] = b2b[tid];

    for (int idx = tid; idx < 2048; idx += 256) {
        int m = idx >> 5, q = idx & 31;
        int gm = m0 + m;
        float4 v = make_float4(0.f, 0.f, 0.f, 0.f);
        if (gm < NN) {
            float sc = 1.0f / fmaxf((float)g_cnt[gm], 1.0f);
            float4 s = ((const float4*)(g_sum + (size_t)gm * 128))[q];
            v.x = s.x * sc; v.y = s.y * sc; v.z = s.z * sc; v.w = s.w * sc;
        }
        *(float4*)(sA + m * 136 + q * 4) = v;
    }

    float c1[2][8][4];
#pragma unroll
    for (int mt = 0; mt < 2; mt++)
#pragma unroll
        for (int nt = 0; nt < 8; nt++)
#pragma unroll
            for (int q = 0; q < 4; q++) c1[mt][nt][q] = 0.f;

    for (int kc = 0; kc < 4; kc++) {
        __syncthreads();
        {
            const uint4* src = (const uint4*)(g_W2m + tid * 128 + kc * 32);
            uint4* dst = (uint4*)(sm + SM_B + tid * 80);
#pragma unroll
            for (int q = 0; q < 4; q++) dst[q] = src[q];
        }
        __syncthreads();
#pragma unroll
        for (int ks = 0; ks < 2; ks++) {
            const int kg = kc * 32 + ks * 16;
            uint32_t af[2][4];
#pragma unroll
            for (int mt = 0; mt < 2; mt++) {
                const float* base = sA + (wm * 32 + mt * 16 + rbase) * 136 + kg + cpos;
                af[mt][0] = f2h2(*(const float2*)(base));
                af[mt][1] = f2h2(*(const float2*)(base + 8 * 136));
                af[mt][2] = f2h2(*(const float2*)(base + 8));
                af[mt][3] = f2h2(*(const float2*)(base + 8 * 136 + 8));
            }
            uint32_t bf[8][2];
            const uint32_t klb = (uint32_t)(ks * 16 + gk) * 2;
#pragma unroll
            for (int ntp = 0; ntp < 4; ntp++) {
                uint32_t off = (uint32_t)(wn * 64 + ntp * 16 + gn + r8) * 80 + klb;
                ldmx4(bf[2*ntp][0], bf[2*ntp][1], bf[2*ntp+1][0], bf[2*ntp+1][1], uB + off);
            }
#pragma unroll
            for (int mt = 0; mt < 2; mt++)
#pragma unroll
                for (int nt = 0; nt < 8; nt++)
                    mma_f16(c1[mt][nt], af[mt], bf[nt]);
        }
    }
    __syncthreads();

#pragma unroll
    for (int mt = 0; mt < 2; mt++) {
        int r0 = wm * 32 + mt * 16 + rbase, r1 = r0 + 8;
        int gm0 = m0 + r0, gm1 = m0 + r1;
        const float* T0 = g_T + (size_t)gm0 * 256;
        const float* T1 = g_T + (size_t)gm1 * 256;
        const float* U0 = g_UG + (size_t)sBt[r0] * 256;
        const float* U1 = g_UG + (size_t)sBt[r1] * 256;
#pragma unroll
        for (int nt = 0; nt < 8; nt++) {
            int col = wn * 64 + nt * 8 + cpos;
            float2 v0 = make_float2(0.f, 0.f), v1 = make_float2(0.f, 0.f);
            if (gm0 < NN) {
                float2 t = *(const float2*)(T0 + col);
                float2 ug = *(const float2*)(U0 + col);
                v0.x = fmaxf(c1[mt][nt][0] + t.x + ug.x, 0.f);
                v0.y = fmaxf(c1[mt][nt][1] + t.y + ug.y, 0.f);
            }
            if (gm1 < NN) {
                float2 t = *(const float2*)(T1 + col);
                float2 ug = *(const float2*)(U1 + col);
                v1.x = fmaxf(c1[mt][nt][2] + t.x + ug.x, 0.f);
                v1.y = fmaxf(c1[mt][nt][3] + t.y + ug.y, 0.f);
            }
            *(uint32_t*)(sH + r0 * 264 + col) = f2h2(v0);
            *(uint32_t*)(sH + r1 * 264 + col) = f2h2(v1);
        }
    }

    float c2[2][4][4];
#pragma unroll
    for (int mt = 0; mt < 2; mt++)
#pragma unroll
        for (int nt = 0; nt < 4; nt++)
#pragma unroll
            for (int q = 0; q < 4; q++) c2[mt][nt][q] = 0.f;

    for (int kc = 0; kc < 8; kc++) {
        __syncthreads();
        {
            int rown = tid & 127, half_ = tid >> 7;
            const uint4* src = (const uint4*)(g_W2bT + rown * 256 + kc * 32) + half_ * 2;
            uint4* dst = (uint4*)(sm + SM_B + rown * 80) + half_ * 2;
            dst[0] = src[0]; dst[1] = src[1];
        }
        __syncthreads();
#pragma unroll
        for (int ks = 0; ks < 2; ks++) {
            const int kg = kc * 32 + ks * 16;
            uint32_t af[2][4];
#pragma unroll
            for (int mt = 0; mt < 2; mt++) {
                const __half* hb = sH + (wm * 32 + mt * 16 + rbase) * 264 + kg + cpos;
                af[mt][0] = *(const uint32_t*)(hb);
                af[mt][1] = *(const uint32_t*)(hb + 8 * 264);
                af[mt][2] = *(const uint32_t*)(hb + 8);
                af[mt][3] = *(const uint32_t*)(hb + 8 * 264 + 8);
            }
            uint32_t bf[4][2];
            const uint32_t klb = (uint32_t)(ks * 16 + gk) * 2;
#pragma unroll
            for (int ntp = 0; ntp < 2; ntp++) {
                uint32_t off = (uint32_t)(wn * 32 + ntp * 16 + gn + r8) * 80 + klb;
                ldmx4(bf[2*ntp][0], bf[2*ntp][1], bf[2*ntp+1][0], bf[2*ntp+1][1], uB + off);
            }
#pragma unroll
            for (int mt = 0; mt < 2; mt++)
#pragma unroll
                for (int nt = 0; nt < 4; nt++)
                    mma_f16(c2[mt][nt], af[mt], bf[nt]);
        }
    }

#pragma unroll
    for (int mt = 0; mt < 2; mt++) {
        int r0 = wm * 32 + mt * 16 + rbase, r1 = r0 + 8;
        int gm0 = m0 + r0, gm1 = m0 + r1;
#pragma unroll
        for (int nt = 0; nt < 4; nt++) {
            int col = wn * 32 + nt * 8 + cpos;
            if (gm0 < NN) {
                float2 v; v.x = c2[mt][nt][0] + sB2b[col]; v.y = c2[mt][nt][1] + sB2b[col + 1];
                *(float2*)(out + (size_t)gm0 * 128 + col) = v;
            }
            if (gm1 < NN) {
                float2 v; v.x = c2[mt][nt][2] + sB2b[col]; v.y = c2[mt][nt][3] + sB2b[col + 1];
                *(float2*)(out + (size_t)gm1 * 128 + col) = v;
            }
        }
    }
}

// ============================================================================
// prep: transposed fp16 weights
// ============================================================================
__global__ void prep_w(const float* __restrict__ W1a, const float* __restrict__ W1b,
                       const float* __restrict__ W2a, const float* __restrict__ W2b) {
    int i = blockIdx.x * blockDim.x + threadIdx.x;
    int st = gridDim.x * blockDim.x;
    for (int idx = i; idx < 256 * 128; idx += st) {
        int n = idx >> 7, k = idx & 127;
        g_W1f[idx] = __float2half_rn(W1a[(128 + k) * 256 + n]);
        g_W1t[idx] = __float2half_rn(W1a[k * 256 + n]);
        g_W2t[idx] = __float2half_rn(W2a[k * 256 + n]);
        g_W2m[idx] = __float2half_rn(W2a[(128 + k) * 256 + n]);
    }
    for (int idx = i; idx < 128 * 256; idx += st) {
        int n = idx >> 8, k = idx & 255;
        g_W2f[idx]  = __float2half_rn(W1b[k * 128 + n]);
        g_W2bT[idx] = __float2half_rn(W2b[k * 128 + n]);
    }
}

// ---------------- scalar UG gemm (grid=1 only) ------------------------------
#define SA_STRIDE  132
#define SA_FLOATS  (64 * SA_STRIDE)
#define SWC_OFF    SA_FLOATS
#define SMEM_FLOATS (SWC_OFF + 32 * 256)
#define SMEM_BYTES  (SMEM_FLOATS * 4)

__device__ __forceinline__ void p1_chunk(const float* __restrict__ sA,
                                         const float* __restrict__ sWc,
                                         unsigned long long acc[4][8],
                                         int kb, int tx, int ty) {
#pragma unroll 4
    for (int k2 = 0; k2 < 32; k2++) {
        unsigned long long a2[4];
#pragma unroll
        for (int i = 0; i < 4; i++)
            a2[i] = dup2(sA[(ty * 4 + i) * SA_STRIDE + kb + k2]);
        const float* wr = sWc + k2 * 256 + tx * 2;
#pragma unroll
        for (int j = 0; j < 8; j++) {
            unsigned long long w2 = *(const unsigned long long*)(wr + j * 32);
#pragma unroll
            for (int i = 0; i < 4; i++) acc[i][j] = ffma2(a2[i], w2, acc[i][j]);
        }
    }
}

__global__ __launch_bounds__(256, 2)
void gemm_k128(const float* __restrict__ A, int M,
               const float* __restrict__ W,
               const float* __restrict__ bias,
               float* __restrict__ out) {
    extern __shared__ float smemf[];
    float* sA  = smemf;
    float* sWc = smemf + SWC_OFF;
    int tid = threadIdx.x;
    int tx = tid & 15, ty = tid >> 4;
    int m0 = blockIdx.x * 64;

    for (int idx = tid; idx < 2048; idx += 256) {
        int m = idx >> 5, kq = idx & 31;
        int gm = m0 + m;
        float4 v = make_float4(0.f, 0.f, 0.f, 0.f);
        if (gm < M) v = ((const float4*)(A + (size_t)gm * 128))[kq];
        *(float4*)(sA + m * SA_STRIDE + kq * 4) = v;
    }

    unsigned long long acc[4][8];
#pragma unroll
    for (int i = 0; i < 4; i++)
#pragma unroll
        for (int j = 0; j < 8; j++) acc[i][j] = 0ULL;

    for (int kb = 0; kb < 128; kb += 32) {
        __syncthreads();
        const float4* wsrc = (const float4*)(W + (size_t)kb * 256);
        for (int idx = tid; idx < 2048; idx += 256)
            ((float4*)sWc)[idx] = wsrc[idx];
        __syncthreads();
        p1_chunk(sA, sWc, acc, kb, tx, ty);
    }

#pragma unroll
    for (int i = 0; i < 4; i++) {
        int gm = m0 + ty * 4 + i;
        if (gm >= M) continue;
        float* orow = out + (size_t)gm * 256;
#pragma unroll
        for (int j = 0; j < 8; j++) {
            int c = j * 32 + tx * 2;
            float2 v = ull2f2(acc[i][j]);
            if (bias) { v.x += bias[c]; v.y += bias[c + 1]; }
            *(float2*)(orow + c) = v;
        }
    }
}

// ============================================================================
__global__ void zero_kernel() {
    int idx = blockIdx.x * blockDim.x + threadIdx.x;
    int stride = gridDim.x * blockDim.x;
    float4 z = make_float4(0.f, 0.f, 0.f, 0.f);
    for (int i = idx; i < NN * 32; i += stride) ((float4*)g_sum)[i] = z;
    for (int i = idx; i < NN; i += stride) g_cnt[i] = 0;
}

// ============================================================================
extern "C" void kernel_launch(void* const* d_in, const int* in_sizes, int n_in,
                              void* d_out, int out_size) {
    const float* x     = (const float*)d_in[0];
    const int*   ei    = (const int*)d_in[1];     // int32 (JAX x64 disabled)
    const float* ea    = (const float*)d_in[2];
    const float* u     = (const float*)d_in[3];
    const int*   batch = (const int*)d_in[4];
    const float* W1a   = (const float*)d_in[5];
    const float* b1a   = (const float*)d_in[6];
    const float* W1b   = (const float*)d_in[7];
    const float* b1b   = (const float*)d_in[8];
    const float* W2a   = (const float*)d_in[9];
    const float* b2a   = (const float*)d_in[10];
    const float* W2b   = (const float*)d_in[11];
    const float* b2b   = (const float*)d_in[12];
    float* out = (float*)d_out;

    cudaFuncSetAttribute(gemm_k128, cudaFuncAttributeMaxDynamicSharedMemorySize, SMEM_BYTES);
    cudaFuncSetAttribute(edge_tc,   cudaFuncAttributeMaxDynamicSharedMemorySize, SMEM_E);
    cudaFuncSetAttribute(pt_tc,     cudaFuncAttributeMaxDynamicSharedMemorySize, SMEM_PT);
    cudaFuncSetAttribute(node_tc,   cudaFuncAttributeMaxDynamicSharedMemorySize, SMEM_N);

    void* pUG;
    cudaGetSymbolAddress(&pUG, g_UG);

    zero_kernel<<<256, 256>>>();
    prep_w<<<128, 256>>>(W1a, W1b, W2a, W2b);

    // P = x@W1a_top + b1a ; T = x@W2a_top + b2a    (fp16 mma)
    pt_tc<<<(NN + 63) / 64, 256, SMEM_PT>>>(x, b1a, b2a);
    // UG = u @ W2a[256:384,:]   (scalar, grid=1)
    gemm_k128<<<1, 256, SMEM_BYTES>>>(u, NG, W2a + 256 * 256, nullptr, (float*)pUG);

    edge_tc<<<EDGE_GRID, 512, SMEM_E>>>(ea, ei, b1b);

    node_tc<<<(NN + 63) / 64, 256, SMEM_N>>>(batch, b2b, out);
}

// round 15
// speedup vs baseline: 3.8317x; 1.1001x over previous
#include <cuda_runtime.h>
#include <cuda_fp16.h>
#include <cstdint>

#define NN 50000
#define NE 800000
#define NG 64

// ---------------- scratch (device globals; no allocation allowed) ----------
__device__ float g_P [NN * 256];   // x @ W1a[0:128,:] + b1a
__device__ float g_T [NN * 256];   // x @ W2a[0:128,:] + b2a
__device__ float g_UG[NG * 256];   // u @ W2a[256:384,:]
__device__ float g_sum[NN * 128];  // scatter-sum of edge MLP output
__device__ int   g_cnt[NN];        // in-degree
// fp16 transposed weights for the tensor-core kernels
__device__ __half g_W1f [256 * 128];  // [n][k] = W1a[128+k][n]  (edge phase1)
__device__ __half g_W2f [128 * 256];  // [n][k] = W1b[k][n]      (edge phase2)
__device__ __half g_W1t [256 * 128];  // [n][k] = W1a[k][n]      (pt phase A)
__device__ __half g_W2t [256 * 128];  // [n][k] = W2a[k][n]      (pt phase B)
__device__ __half g_W2g [256 * 128];  // [n][k] = W2a[256+k][n]  (pt UG phase)
__device__ __half g_W2m [256 * 128];  // [n][k] = W2a[128+k][n]  (node phase1)
__device__ __half g_W2bT[128 * 256];  // [n][k] = W2b[k][n]      (node phase2)

// ---------------- mma.sync helpers ------------------------------------------
__device__ __forceinline__ uint32_t smem_u32(const void* p) {
    uint32_t a;
    asm("{ .reg .u64 t; cvta.to.shared.u64 t, %1; cvt.u32.u64 %0, t; }"
        : "=r"(a) : "l"(p));
    return a;
}
__device__ __forceinline__ void ldmx4(uint32_t& r0, uint32_t& r1,
                                      uint32_t& r2, uint32_t& r3, uint32_t addr) {
    asm volatile("ldmatrix.sync.aligned.m8n8.x4.shared.b16 {%0,%1,%2,%3}, [%4];"
                 : "=r"(r0), "=r"(r1), "=r"(r2), "=r"(r3) : "r"(addr));
}
__device__ __forceinline__ void mma_f16(float c[4], const uint32_t a[4],
                                        const uint32_t b[2]) {
    asm volatile(
        "mma.sync.aligned.m16n8k16.row.col.f32.f16.f16.f32 "
        "{%0,%1,%2,%3}, {%4,%5,%6,%7}, {%8,%9}, {%0,%1,%2,%3};"
        : "+f"(c[0]), "+f"(c[1]), "+f"(c[2]), "+f"(c[3])
        : "r"(a[0]), "r"(a[1]), "r"(a[2]), "r"(a[3]), "r"(b[0]), "r"(b[1]));
}
// pack float2 -> half2 (x -> low half)
__device__ __forceinline__ uint32_t f2h2(float2 v) {
    uint32_t r;
    asm("cvt.rn.f16x2.f32 %0, %1, %2;" : "=r"(r) : "f"(v.y), "f"(v.x));
    return r;
}

// ============================================================================
// Persistent edge kernel smem layout (bytes):
//   SM_AH : A fp16 [128][136] = 34816 ; aliased H fp16 [128][264] = 67584
//   SM_W1 : W1f fp16 [256][136] = 69632  (persistent, ldmatrix-padded)
//   SM_W2 : W2f fp16 [128][264] = 67584  (persistent)
//   SM_EI/SM_CD : double-buffered index arrays [2][128]
// ============================================================================
#define SM_AH  0
#define SM_W1  67584
#define SM_W2  137216
#define SM_EI  204800
#define SM_CD  205824
#define SM_B1B 206848
#define SMEM_E 207360
#define NTILES (NE / 128)     // 6250
#define EDGE_GRID 152

// ============================================================================
// edge_tc: persistent CTAs, 512 threads (16 warps: wm = wid&3, wn = wid>>2),
// 128 edges/tile. Weights resident in smem; next-tile A prefetched in regs.
//   C1 = EA @ W1f^T (K=128) ; h = relu(C1 + P[row]) -> H (fp16, aliases A)
//   C2 = h @ W2f^T (K=256)  ; scatter-add(C2 + b1b), degree count
// ============================================================================
__global__ __launch_bounds__(512, 1)
void edge_tc(const float* __restrict__ ea,
             const int*   __restrict__ ei,
             const float* __restrict__ b1b) {
    extern __shared__ char sm[];
    __half* sAH = (__half*)(sm + SM_AH);
    int   (*sEi)[128] = (int(*)[128])(sm + SM_EI);
    int   (*sCd)[128] = (int(*)[128])(sm + SM_CD);
    float*  sB1b= (float*)(sm + SM_B1B);
    const uint32_t sbase = smem_u32(sm);
    const uint32_t uW1 = sbase + SM_W1, uW2 = sbase + SM_W2;

    const int tid = threadIdx.x, lane = tid & 31, wid = tid >> 5;
    const int wm = wid & 3, wn = wid >> 2;
    const int rbase = lane >> 2, cpos = 2 * (lane & 3);
    const int g = lane >> 3, r8 = lane & 7;
    const int gk = (g & 1) << 3, gn = (g >> 1) << 3;
    const int pm = tid >> 5, pq0 = tid & 31;   // prefetch: m=pm+16j? no: see below

    // ---- stage weights once (padded strides: W1 136 halfs, W2 264 halfs) ----
    for (int c = tid; c < 4096; c += 512) {
        int row = c >> 4, kp = (c & 15) * 8;
        *(uint4*)(sm + SM_W1 + row * 272 + kp * 2) =
            *(const uint4*)(g_W1f + row * 128 + kp);
    }
    for (int c = tid; c < 4096; c += 512) {
        int row = c >> 5, kp = (c & 31) * 8;
        *(uint4*)(sm + SM_W2 + row * 528 + kp * 2) =
            *(const uint4*)(g_W2f + row * 256 + kp);
    }
    if (tid < 128) sB1b[tid] = b1b[tid];

    // ---- prologue: tile0 indices + A into smem ----
    {
        const int e0 = blockIdx.x * 128;
        if (tid < 128) { sEi[0][tid] = ei[e0 + tid]; sCd[0][tid] = ei[NE + e0 + tid]; }
#pragma unroll
        for (int j = 0; j < 8; j++) {
            int idx = tid + j * 512;
            int m = idx >> 5, q = idx & 31;
            float4 v = ((const float4*)(ea + (size_t)(e0 + m) * 128))[q];
            uint32_t h0 = f2h2(make_float2(v.x, v.y));
            uint32_t h1 = f2h2(make_float2(v.z, v.w));
            *(uint2*)(sm + SM_AH + (m * 136 + q * 4) * 2) = make_uint2(h0, h1);
        }
    }

    int it = 0;
    for (int tile = blockIdx.x; tile < NTILES; tile += gridDim.x, it ^= 1) {
        __syncthreads();   // A(cur) + indices + weights visible

        // ---------------- phase 1: C1[128][256] = A @ W1f^T (K=128) ---------
        float c1[2][8][4];
#pragma unroll
        for (int mt = 0; mt < 2; mt++)
#pragma unroll
            for (int nt = 0; nt < 8; nt++)
#pragma unroll
                for (int q = 0; q < 4; q++) c1[mt][nt][q] = 0.f;

#pragma unroll 2
        for (int kc = 0; kc < 8; kc++) {
            const int kg = kc * 16;
            uint32_t af[2][4];
#pragma unroll
            for (int mt = 0; mt < 2; mt++) {
                const __half* hb = sAH + (wm * 32 + mt * 16 + rbase) * 136 + kg + cpos;
                af[mt][0] = *(const uint32_t*)(hb);
                af[mt][1] = *(const uint32_t*)(hb + 8 * 136);
                af[mt][2] = *(const uint32_t*)(hb + 8);
                af[mt][3] = *(const uint32_t*)(hb + 8 * 136 + 8);
            }
            uint32_t bf[8][2];
#pragma unroll
            for (int ntp = 0; ntp < 4; ntp++) {
                uint32_t off = (uint32_t)(wn * 64 + ntp * 16 + gn + r8) * 272
                             + (uint32_t)(kg + gk) * 2;
                ldmx4(bf[2*ntp][0], bf[2*ntp][1], bf[2*ntp+1][0], bf[2*ntp+1][1], uW1 + off);
            }
#pragma unroll
            for (int mt = 0; mt < 2; mt++)
#pragma unroll
                for (int nt = 0; nt < 8; nt++)
                    mma_f16(c1[mt][nt], af[mt], bf[nt]);
        }
        __syncthreads();   // phase-1 reads of A done before H overwrites

        // ------- epilogue 1: h = relu(C1 + P[row]) -> H fp16 [128][264] -----
#pragma unroll
        for (int mt = 0; mt < 2; mt++) {
            int r0 = wm * 32 + mt * 16 + rbase, r1 = r0 + 8;
            const float* P0 = g_P + (size_t)sEi[it][r0] * 256;
            const float* P1 = g_P + (size_t)sEi[it][r1] * 256;
#pragma unroll
            for (int nt = 0; nt < 8; nt++) {
                int col = wn * 64 + nt * 8 + cpos;
                float2 q0 = *(const float2*)(P0 + col);
                float2 q1 = *(const float2*)(P1 + col);
                float2 v0, v1;
                v0.x = fmaxf(c1[mt][nt][0] + q0.x, 0.f);
                v0.y = fmaxf(c1[mt][nt][1] + q0.y, 0.f);
                v1.x = fmaxf(c1[mt][nt][2] + q1.x, 0.f);
                v1.y = fmaxf(c1[mt][nt][3] + q1.y, 0.f);
                *(uint32_t*)(sAH + r0 * 264 + col) = f2h2(v0);
                *(uint32_t*)(sAH + r1 * 264 + col) = f2h2(v1);
            }
        }
        __syncthreads();   // H fully written before phase 2 reads

        // ------- phase 2 (+ prefetch next tile A into regs, idx into smem) --
        const int ntile = tile + gridDim.x;
        const bool hn = ntile < NTILES;
        float4 pref[8];
        if (hn) {
            const int e0n = ntile * 128;
#pragma unroll
            for (int j = 0; j < 8; j++) {
                int idx = tid + j * 512;
                int m = idx >> 5, q = idx & 31;
                pref[j] = ((const float4*)(ea + (size_t)(e0n + m) * 128))[q];
            }
            if (tid < 128) {
                sEi[it ^ 1][tid] = ei[e0n + tid];
                sCd[it ^ 1][tid] = ei[NE + e0n + tid];
            }
        }

        float c2[2][4][4];
#pragma unroll
        for (int mt = 0; mt < 2; mt++)
#pragma unroll
            for (int nt = 0; nt < 4; nt++)
#pragma unroll
                for (int q = 0; q < 4; q++) c2[mt][nt][q] = 0.f;

#pragma unroll 2
        for (int kc = 0; kc < 16; kc++) {
            const int kg = kc * 16;
            uint32_t af[2][4];
#pragma unroll
            for (int mt = 0; mt < 2; mt++) {
                const __half* hb = sAH + (wm * 32 + mt * 16 + rbase) * 264 + kg + cpos;
                af[mt][0] = *(const uint32_t*)(hb);
                af[mt][1] = *(const uint32_t*)(hb + 8 * 264);
                af[mt][2] = *(const uint32_t*)(hb + 8);
                af[mt][3] = *(const uint32_t*)(hb + 8 * 264 + 8);
            }
            uint32_t bf[4][2];
#pragma unroll
            for (int ntp = 0; ntp < 2; ntp++) {
                uint32_t off = (uint32_t)(wn * 32 + ntp * 16 + gn + r8) * 528
                             + (uint32_t)(kg + gk) * 2;
                ldmx4(bf[2*ntp][0], bf[2*ntp][1], bf[2*ntp+1][0], bf[2*ntp+1][1], uW2 + off);
            }
#pragma unroll
            for (int mt = 0; mt < 2; mt++)
#pragma unroll
                for (int nt = 0; nt < 4; nt++)
                    mma_f16(c2[mt][nt], af[mt], bf[nt]);
        }
        __syncthreads();   // H reads done; safe to overwrite with A(next)

        // ---- store prefetched A(next) (overlaps epi2 atomics) ----
        if (hn) {
#pragma unroll
            for (int j = 0; j < 8; j++) {
                int idx = tid + j * 512;
                int m = idx >> 5, q = idx & 31;
                uint32_t h0 = f2h2(make_float2(pref[j].x, pref[j].y));
                uint32_t h1 = f2h2(make_float2(pref[j].z, pref[j].w));
                *(uint2*)(sm + SM_AH + (m * 136 + q * 4) * 2) = make_uint2(h0, h1);
            }
        }

        // ---------------- epilogue 2: scatter-add + degree ----------------
#pragma unroll
        for (int mt = 0; mt < 2; mt++) {
            int r0 = wm * 32 + mt * 16 + rbase, r1 = r0 + 8;
            float* s0 = g_sum + (size_t)sCd[it][r0] * 128;
            float* s1 = g_sum + (size_t)sCd[it][r1] * 128;
#pragma unroll
            for (int nt = 0; nt < 4; nt++) {
                int col = wn * 32 + nt * 8 + cpos;
                atomicAdd(s0 + col,     c2[mt][nt][0] + sB1b[col]);
                atomicAdd(s0 + col + 1, c2[mt][nt][1] + sB1b[col + 1]);
                atomicAdd(s1 + col,     c2[mt][nt][2] + sB1b[col]);
                atomicAdd(s1 + col + 1, c2[mt][nt][3] + sB1b[col + 1]);
            }
        }
        if (wn == 0 && (lane & 3) == 0) {
#pragma unroll
            for (int q = 0; q < 4; q++)
                atomicAdd(&g_cnt[sCd[it][wm * 32 + q * 8 + rbase]], 1);
        }
    }
}

// ---------------- pt/node kernels: 64-row tiles, 256 threads ----------------
#define SM_A   0        // A fp32 [64][136]=34816 ; H fp16 [64][264]=33792
#define SM_B   34816    // fp16 [256][40] = 20480
#define SM_PTBA 55296
#define SM_PTBB 56320
#define SMEM_PT 57344
#define PT_GRID ((NN + 63) / 64 + 1)   // 783: last CTA computes UG

// ============================================================================
// pt_tc: per-CTA x-tile [64][128]; two phase-1 passes:
//   P = x @ W1t^T + b1a ;  T = x @ W2t^T + b2a    (both K=128, N=256)
// Last CTA instead computes UG = u @ W2g^T  (M=64=NG, one pass, no bias).
// ============================================================================
__global__ __launch_bounds__(256)
void pt_tc(const float* __restrict__ x,
           const float* __restrict__ u,
           const float* __restrict__ b1a,
           const float* __restrict__ b2a) {
    extern __shared__ char sm[];
    float* sA = (float*)(sm + SM_A);
    float* sBa = (float*)(sm + SM_PTBA);
    float* sBb = (float*)(sm + SM_PTBB);
    const uint32_t uB = smem_u32(sm) + SM_B;

    const int tid = threadIdx.x, lane = tid & 31, wid = tid >> 5;
    const int wm = wid & 1, wn = wid >> 1;
    const int rbase = lane >> 2, cpos = 2 * (lane & 3);
    const int g = lane >> 3, r8 = lane & 7;
    const int gk = (g & 1) << 3, gn = (g >> 1) << 3;

    // ---------------- UG special CTA ----------------
    if (blockIdx.x == PT_GRID - 1) {
        for (int idx = tid; idx < 2048; idx += 256) {
            int m = idx >> 5, q = idx & 31;
            *(float4*)(sA + m * 136 + q * 4) = ((const float4*)(u + (size_t)m * 128))[q];
        }
        float c1[2][8][4];
#pragma unroll
        for (int mt = 0; mt < 2; mt++)
#pragma unroll
            for (int nt = 0; nt < 8; nt++)
#pragma unroll
                for (int q = 0; q < 4; q++) c1[mt][nt][q] = 0.f;

        for (int kc = 0; kc < 4; kc++) {
            __syncthreads();
            {
                const uint4* src = (const uint4*)(g_W2g + tid * 128 + kc * 32);
                uint4* d = (uint4*)(sm + SM_B + tid * 80);
#pragma unroll
                for (int q = 0; q < 4; q++) d[q] = src[q];
            }
            __syncthreads();
#pragma unroll
            for (int ks = 0; ks < 2; ks++) {
                const int kg = kc * 32 + ks * 16;
                uint32_t af[2][4];
#pragma unroll
                for (int mt = 0; mt < 2; mt++) {
                    const float* base = sA + (wm * 32 + mt * 16 + rbase) * 136 + kg + cpos;
                    af[mt][0] = f2h2(*(const float2*)(base));
                    af[mt][1] = f2h2(*(const float2*)(base + 8 * 136));
                    af[mt][2] = f2h2(*(const float2*)(base + 8));
                    af[mt][3] = f2h2(*(const float2*)(base + 8 * 136 + 8));
                }
                uint32_t bf[8][2];
                const uint32_t klb = (uint32_t)(ks * 16 + gk) * 2;
#pragma unroll
                for (int ntp = 0; ntp < 4; ntp++) {
                    uint32_t off = (uint32_t)(wn * 64 + ntp * 16 + gn + r8) * 80 + klb;
                    ldmx4(bf[2*ntp][0], bf[2*ntp][1], bf[2*ntp+1][0], bf[2*ntp+1][1], uB + off);
                }
#pragma unroll
                for (int mt = 0; mt < 2; mt++)
#pragma unroll
                    for (int nt = 0; nt < 8; nt++)
                        mma_f16(c1[mt][nt], af[mt], bf[nt]);
            }
        }
#pragma unroll
        for (int mt = 0; mt < 2; mt++) {
            int r0 = wm * 32 + mt * 16 + rbase, r1 = r0 + 8;
#pragma unroll
            for (int nt = 0; nt < 8; nt++) {
                int col = wn * 64 + nt * 8 + cpos;
                *(float2*)(g_UG + (size_t)r0 * 256 + col) = make_float2(c1[mt][nt][0], c1[mt][nt][1]);
                *(float2*)(g_UG + (size_t)r1 * 256 + col) = make_float2(c1[mt][nt][2], c1[mt][nt][3]);
            }
        }
        return;
    }

    const int m0 = blockIdx.x * 64;
    sBa[tid] = b1a[tid];
    sBb[tid] = b2a[tid];

    for (int idx = tid; idx < 2048; idx += 256) {
        int m = idx >> 5, q = idx & 31;
        int gm = m0 + m;
        float4 v = make_float4(0.f, 0.f, 0.f, 0.f);
        if (gm < NN) v = ((const float4*)(x + (size_t)gm * 128))[q];
        *(float4*)(sA + m * 136 + q * 4) = v;
    }

    for (int ph = 0; ph < 2; ph++) {
        const __half* W = ph ? g_W2t : g_W1t;
        const float* bias = ph ? sBb : sBa;
        float* dst = ph ? g_T : g_P;

        float c1[2][8][4];
#pragma unroll
        for (int mt = 0; mt < 2; mt++)
#pragma unroll
            for (int nt = 0; nt < 8; nt++)
#pragma unroll
                for (int q = 0; q < 4; q++) c1[mt][nt][q] = 0.f;

        for (int kc = 0; kc < 4; kc++) {
            __syncthreads();
            {
                const uint4* src = (const uint4*)(W + tid * 128 + kc * 32);
                uint4* d = (uint4*)(sm + SM_B + tid * 80);
#pragma unroll
                for (int q = 0; q < 4; q++) d[q] = src[q];
            }
            __syncthreads();
#pragma unroll
            for (int ks = 0; ks < 2; ks++) {
                const int kg = kc * 32 + ks * 16;
                uint32_t af[2][4];
#pragma unroll
                for (int mt = 0; mt < 2; mt++) {
                    const float* base = sA + (wm * 32 + mt * 16 + rbase) * 136 + kg + cpos;
                    af[mt][0] = f2h2(*(const float2*)(base));
                    af[mt][1] = f2h2(*(const float2*)(base + 8 * 136));
                    af[mt][2] = f2h2(*(const float2*)(base + 8));
                    af[mt][3] = f2h2(*(const float2*)(base + 8 * 136 + 8));
                }
                uint32_t bf[8][2];
                const uint32_t klb = (uint32_t)(ks * 16 + gk) * 2;
#pragma unroll
                for (int ntp = 0; ntp < 4; ntp++) {
                    uint32_t off = (uint32_t)(wn * 64 + ntp * 16 + gn + r8) * 80 + klb;
                    ldmx4(bf[2*ntp][0], bf[2*ntp][1], bf[2*ntp+1][0], bf[2*ntp+1][1], uB + off);
                }
#pragma unroll
                for (int mt = 0; mt < 2; mt++)
#pragma unroll
                    for (int nt = 0; nt < 8; nt++)
                        mma_f16(c1[mt][nt], af[mt], bf[nt]);
            }
        }
        __syncthreads();

#pragma unroll
        for (int mt = 0; mt < 2; mt++) {
            int r0 = wm * 32 + mt * 16 + rbase, r1 = r0 + 8;
            int gm0 = m0 + r0, gm1 = m0 + r1;
#pragma unroll
            for (int nt = 0; nt < 8; nt++) {
                int col = wn * 64 + nt * 8 + cpos;
                if (gm0 < NN) {
                    float2 v; v.x = c1[mt][nt][0] + bias[col]; v.y = c1[mt][nt][1] + bias[col + 1];
                    *(float2*)(dst + (size_t)gm0 * 256 + col) = v;
                }
                if (gm1 < NN) {
                    float2 v; v.x = c1[mt][nt][2] + bias[col]; v.y = c1[mt][nt][3] + bias[col + 1];
                    *(float2*)(dst + (size_t)gm1 * 256 + col) = v;
                }
            }
        }
    }
}

// ---------------- node kernel smem layout --------------------------------
#define SM_NBATCH 55296
#define SM_NB2B   55552
#define SMEM_N    56064

// ============================================================================
// node_tc: 64 nodes/CTA
//   C1 = agg @ W2m^T (K=128); h = relu(C1 + T[gm] + UG[batch]) -> sH
//   C2 = h @ W2bT^T (K=256) ; out[gm] = C2 + b2b
// ============================================================================
__global__ __launch_bounds__(256)
void node_tc(const int* __restrict__ batch,
             const float* __restrict__ b2b,
             float* __restrict__ out) {
    extern __shared__ char sm[];
    float*  sA  = (float*)(sm + SM_A);
    __half* sH  = (__half*)(sm + SM_A);
    int*    sBt = (int*)(sm + SM_NBATCH);
    float*  sB2b= (float*)(sm + SM_NB2B);
    const uint32_t uB = smem_u32(sm) + SM_B;

    const int tid = threadIdx.x, lane = tid & 31, wid = tid >> 5;
    const int m0 = blockIdx.x * 64;
    const int wm = wid & 1, wn = wid >> 1;
    const int rbase = lane >> 2, cpos = 2 * (lane & 3);
    const int g = lane >> 3, r8 = lane & 7;
    const int gk = (g & 1) << 3, gn = (g >> 1) << 3;

    if (tid < 64) sBt[tid] = (m0 + tid < NN) ? batch[m0 + tid] : 0;
    if (tid < 128) sB2b[tid] = b2b[tid];

    for (int idx = tid; idx < 2048; idx += 256) {
        int m = idx >> 5, q = idx & 31;
        int gm = m0 + m;
        float4 v = make_float4(0.f, 0.f, 0.f, 0.f);
        if (gm < NN) {
            float sc = 1.0f / fmaxf((float)g_cnt[gm], 1.0f);
            float4 s = ((const float4*)(g_sum + (size_t)gm * 128))[q];
            v.x = s.x * sc; v.y = s.y * sc; v.z = s.z * sc; v.w = s.w * sc;
        }
        *(float4*)(sA + m * 136 + q * 4) = v;
    }

    float c1[2][8][4];
#pragma unroll
    for (int mt = 0; mt < 2; mt++)
#pragma unroll
        for (int nt = 0; nt < 8; nt++)
#pragma unroll
            for (int q = 0; q < 4; q++) c1[mt][nt][q] = 0.f;

    for (int kc = 0; kc < 4; kc++) {
        __syncthreads();
        {
            const uint4* src = (const uint4*)(g_W2m + tid * 128 + kc * 32);
            uint4* dst = (uint4*)(sm + SM_B + tid * 80);
#pragma unroll
            for (int q = 0; q < 4; q++) dst[q] = src[q];
        }
        __syncthreads();
#pragma unroll
        for (int ks = 0; ks < 2; ks++) {
            const int kg = kc * 32 + ks * 16;
            uint32_t af[2][4];
#pragma unroll
            for (int mt = 0; mt < 2; mt++) {
                const float* base = sA + (wm * 32 + mt * 16 + rbase) * 136 + kg + cpos;
                af[mt][0] = f2h2(*(const float2*)(base));
                af[mt][1] = f2h2(*(const float2*)(base + 8 * 136));
                af[mt][2] = f2h2(*(const float2*)(base + 8));
                af[mt][3] = f2h2(*(const float2*)(base + 8 * 136 + 8));
            }
            uint32_t bf[8][2];
            const uint32_t klb = (uint32_t)(ks * 16 + gk) * 2;
#pragma unroll
            for (int ntp = 0; ntp < 4; ntp++) {
                uint32_t off = (uint32_t)(wn * 64 + ntp * 16 + gn + r8) * 80 + klb;
                ldmx4(bf[2*ntp][0], bf[2*ntp][1], bf[2*ntp+1][0], bf[2*ntp+1][1], uB + off);
            }
#pragma unroll
            for (int mt = 0; mt < 2; mt++)
#pragma unroll
                for (int nt = 0; nt < 8; nt++)
                    mma_f16(c1[mt][nt], af[mt], bf[nt]);
        }
    }
    __syncthreads();

#pragma unroll
    for (int mt = 0; mt < 2; mt++) {
        int r0 = wm * 32 + mt * 16 + rbase, r1 = r0 + 8;
        int gm0 = m0 + r0, gm1 = m0 + r1;
        const float* T0 = g_T + (size_t)gm0 * 256;
        const float* T1 = g_T + (size_t)gm1 * 256;
        const float* U0 = g_UG + (size_t)sBt[r0] * 256;
        const float* U1 = g_UG + (size_t)sBt[r1] * 256;
#pragma unroll
        for (int nt = 0; nt < 8; nt++) {
            int col = wn * 64 + nt * 8 + cpos;
            float2 v0 = make_float2(0.f, 0.f), v1 = make_float2(0.f, 0.f);
            if (gm0 < NN) {
                float2 t = *(const float2*)(T0 + col);
                float2 ug = *(const float2*)(U0 + col);
                v0.x = fmaxf(c1[mt][nt][0] + t.x + ug.x, 0.f);
                v0.y = fmaxf(c1[mt][nt][1] + t.y + ug.y, 0.f);
            }
            if (gm1 < NN) {
                float2 t = *(const float2*)(T1 + col);
                float2 ug = *(const float2*)(U1 + col);
                v1.x = fmaxf(c1[mt][nt][2] + t.x + ug.x, 0.f);
                v1.y = fmaxf(c1[mt][nt][3] + t.y + ug.y, 0.f);
            }
            *(uint32_t*)(sH + r0 * 264 + col) = f2h2(v0);
            *(uint32_t*)(sH + r1 * 264 + col) = f2h2(v1);
        }
    }

    float c2[2][4][4];
#pragma unroll
    for (int mt = 0; mt < 2; mt++)
#pragma unroll
        for (int nt = 0; nt < 4; nt++)
#pragma unroll
            for (int q = 0; q < 4; q++) c2[mt][nt][q] = 0.f;

    for (int kc = 0; kc < 8; kc++) {
        __syncthreads();
        {
            int rown = tid & 127, half_ = tid >> 7;
            const uint4* src = (const uint4*)(g_W2bT + rown * 256 + kc * 32) + half_ * 2;
            uint4* dst = (uint4*)(sm + SM_B + rown * 80) + half_ * 2;
            dst[0] = src[0]; dst[1] = src[1];
        }
        __syncthreads();
#pragma unroll
        for (int ks = 0; ks < 2; ks++) {
            const int kg = kc * 32 + ks * 16;
            uint32_t af[2][4];
#pragma unroll
            for (int mt = 0; mt < 2; mt++) {
                const __half* hb = sH + (wm * 32 + mt * 16 + rbase) * 264 + kg + cpos;
                af[mt][0] = *(const uint32_t*)(hb);
                af[mt][1] = *(const uint32_t*)(hb + 8 * 264);
                af[mt][2] = *(const uint32_t*)(hb + 8);
                af[mt][3] = *(const uint32_t*)(hb + 8 * 264 + 8);
            }
            uint32_t bf[4][2];
            const uint32_t klb = (uint32_t)(ks * 16 + gk) * 2;
#pragma unroll
            for (int ntp = 0; ntp < 2; ntp++) {
                uint32_t off = (uint32_t)(wn * 32 + ntp * 16 + gn + r8) * 80 + klb;
                ldmx4(bf[2*ntp][0], bf[2*ntp][1], bf[2*ntp+1][0], bf[2*ntp+1][1], uB + off);
            }
#pragma unroll
            for (int mt = 0; mt < 2; mt++)
#pragma unroll
                for (int nt = 0; nt < 4; nt++)
                    mma_f16(c2[mt][nt], af[mt], bf[nt]);
        }
    }

#pragma unroll
    for (int mt = 0; mt < 2; mt++) {
        int r0 = wm * 32 + mt * 16 + rbase, r1 = r0 + 8;
        int gm0 = m0 + r0, gm1 = m0 + r1;
#pragma unroll
        for (int nt = 0; nt < 4; nt++) {
            int col = wn * 32 + nt * 8 + cpos;
            if (gm0 < NN) {
                float2 v; v.x = c2[mt][nt][0] + sB2b[col]; v.y = c2[mt][nt][1] + sB2b[col + 1];
                *(float2*)(out + (size_t)gm0 * 128 + col) = v;
            }
            if (gm1 < NN) {
                float2 v; v.x = c2[mt][nt][2] + sB2b[col]; v.y = c2[mt][nt][3] + sB2b[col + 1];
                *(float2*)(out + (size_t)gm1 * 128 + col) = v;
            }
        }
    }
}

// ============================================================================
// init: zero accumulators + build all transposed fp16 weights (one launch)
// ============================================================================
__global__ void init_kernel(const float* __restrict__ W1a, const float* __restrict__ W1b,
                            const float* __restrict__ W2a, const float* __restrict__ W2b) {
    int i = blockIdx.x * blockDim.x + threadIdx.x;
    int st = gridDim.x * blockDim.x;
    float4 z = make_float4(0.f, 0.f, 0.f, 0.f);
    for (int idx = i; idx < NN * 32; idx += st) ((float4*)g_sum)[idx] = z;
    for (int idx = i; idx < NN; idx += st) g_cnt[idx] = 0;
    for (int idx = i; idx < 256 * 128; idx += st) {
        int n = idx >> 7, k = idx & 127;
        g_W1f[idx] = __float2half_rn(W1a[(128 + k) * 256 + n]);
        g_W1t[idx] = __float2half_rn(W1a[k * 256 + n]);
        g_W2t[idx] = __float2half_rn(W2a[k * 256 + n]);
        g_W2m[idx] = __float2half_rn(W2a[(128 + k) * 256 + n]);
        g_W2g[idx] = __float2half_rn(W2a[(256 + k) * 256 + n]);
    }
    for (int idx = i; idx < 128 * 256; idx += st) {
        int n = idx >> 8, k = idx & 255;
        g_W2f[idx]  = __float2half_rn(W1b[k * 128 + n]);
        g_W2bT[idx] = __float2half_rn(W2b[k * 128 + n]);
    }
}

// ============================================================================
extern "C" void kernel_launch(void* const* d_in, const int* in_sizes, int n_in,
                              void* d_out, int out_size) {
    const float* x     = (const float*)d_in[0];
    const int*   ei    = (const int*)d_in[1];     // int32 (JAX x64 disabled)
    const float* ea    = (const float*)d_in[2];
    const float* u     = (const float*)d_in[3];
    const int*   batch = (const int*)d_in[4];
    const float* W1a   = (const float*)d_in[5];
    const float* b1a   = (const float*)d_in[6];
    const float* W1b   = (const float*)d_in[7];
    const float* b1b   = (const float*)d_in[8];
    const float* W2a   = (const float*)d_in[9];
    const float* b2a   = (const float*)d_in[10];
    const float* W2b   = (const float*)d_in[11];
    const float* b2b   = (const float*)d_in[12];
    float* out = (float*)d_out;

    cudaFuncSetAttribute(edge_tc, cudaFuncAttributeMaxDynamicSharedMemorySize, SMEM_E);
    cudaFuncSetAttribute(pt_tc,   cudaFuncAttributeMaxDynamicSharedMemorySize, SMEM_PT);
    cudaFuncSetAttribute(node_tc, cudaFuncAttributeMaxDynamicSharedMemorySize, SMEM_N);

    init_kernel<<<128, 256>>>(W1a, W1b, W2a, W2b);

    // P = x@W1a_top + b1a ; T = x@W2a_top + b2a ; UG = u@W2a_glob (last CTA)
    pt_tc<<<PT_GRID, 256, SMEM_PT>>>(x, u, b1a, b2a);

    edge_tc<<<EDGE_GRID, 512, SMEM_E>>>(ea, ei, b1b);

    node_tc<<<(NN + 63) / 64, 256, SMEM_N>>>(batch, b2b, out);
}

// round 16
// speedup vs baseline: 4.0737x; 1.0632x over previous
#include <cuda_runtime.h>
#include <cuda_fp16.h>
#include <cstdint>

#define NN 50000
#define NE 800000
#define NG 64

// ---------------- scratch (device globals; no allocation allowed) ----------
__device__ float g_P [NN * 256];   // x @ W1a[0:128,:] + b1a
__device__ float g_T [NN * 256];   // x @ W2a[0:128,:] + b2a
__device__ float g_UG[NG * 256];   // u @ W2a[256:384,:]  (fp32 exact, in init)
__device__ float g_sum[NN * 128];  // scatter-sum of edge MLP output
__device__ int   g_cnt[NN];        // in-degree
// fp16 transposed weights for the tensor-core kernels
__device__ __half g_W1f [256 * 128];  // [n][k] = W1a[128+k][n]  (edge phase1)
__device__ __half g_W2f [128 * 256];  // [n][k] = W1b[k][n]      (edge phase2)
__device__ __half g_W1t [256 * 128];  // [n][k] = W1a[k][n]      (pt phase A)
__device__ __half g_W2t [256 * 128];  // [n][k] = W2a[k][n]      (pt phase B)
__device__ __half g_W2m [256 * 128];  // [n][k] = W2a[128+k][n]  (node phase1)
__device__ __half g_W2bT[128 * 256];  // [n][k] = W2b[k][n]      (node phase2)

// ---------------- mma.sync helpers ------------------------------------------
__device__ __forceinline__ uint32_t smem_u32(const void* p) {
    uint32_t a;
    asm("{ .reg .u64 t; cvta.to.shared.u64 t, %1; cvt.u32.u64 %0, t; }"
        : "=r"(a) : "l"(p));
    return a;
}
__device__ __forceinline__ void ldmx4(uint32_t& r0, uint32_t& r1,
                                      uint32_t& r2, uint32_t& r3, uint32_t addr) {
    asm volatile("ldmatrix.sync.aligned.m8n8.x4.shared.b16 {%0,%1,%2,%3}, [%4];"
                 : "=r"(r0), "=r"(r1), "=r"(r2), "=r"(r3) : "r"(addr));
}
__device__ __forceinline__ void mma_f16(float c[4], const uint32_t a[4],
                                        const uint32_t b[2]) {
    asm volatile(
        "mma.sync.aligned.m16n8k16.row.col.f32.f16.f16.f32 "
        "{%0,%1,%2,%3}, {%4,%5,%6,%7}, {%8,%9}, {%0,%1,%2,%3};"
        : "+f"(c[0]), "+f"(c[1]), "+f"(c[2]), "+f"(c[3])
        : "r"(a[0]), "r"(a[1]), "r"(a[2]), "r"(a[3]), "r"(b[0]), "r"(b[1]));
}
// pack float2 -> half2 (x -> low half)
__device__ __forceinline__ uint32_t f2h2(float2 v) {
    uint32_t r;
    asm("cvt.rn.f16x2.f32 %0, %1, %2;" : "=r"(r) : "f"(v.y), "f"(v.x));
    return r;
}

// ============================================================================
// Persistent edge kernel smem layout (bytes)
// ============================================================================
#define SM_AH  0
#define SM_W1  67584
#define SM_W2  137216
#define SM_EI  204800
#define SM_CD  205824
#define SM_B1B 206848
#define SMEM_E 207360
#define NTILES (NE / 128)     // 6250
#define EDGE_GRID 152

// ============================================================================
// edge_tc: persistent CTAs, 512 threads (16 warps: wm = wid&3, wn = wid>>2),
// 128 edges/tile. Weights resident in smem; next-tile A prefetched in regs.
//   C1 = EA @ W1f^T (K=128) ; h = relu(C1 + P[row]) -> H (fp16, aliases A)
//   C2 = h @ W2f^T (K=256)  ; scatter-add(C2 + b1b), degree count
// ============================================================================
__global__ __launch_bounds__(512, 1)
void edge_tc(const float* __restrict__ ea,
             const int*   __restrict__ ei,
             const float* __restrict__ b1b) {
    extern __shared__ char sm[];
    __half* sAH = (__half*)(sm + SM_AH);
    int   (*sEi)[128] = (int(*)[128])(sm + SM_EI);
    int   (*sCd)[128] = (int(*)[128])(sm + SM_CD);
    float*  sB1b= (float*)(sm + SM_B1B);
    const uint32_t sbase = smem_u32(sm);
    const uint32_t uW1 = sbase + SM_W1, uW2 = sbase + SM_W2;

    const int tid = threadIdx.x, lane = tid & 31, wid = tid >> 5;
    const int wm = wid & 3, wn = wid >> 2;
    const int rbase = lane >> 2, cpos = 2 * (lane & 3);
    const int g = lane >> 3, r8 = lane & 7;
    const int gk = (g & 1) << 3, gn = (g >> 1) << 3;

    for (int c = tid; c < 4096; c += 512) {
        int row = c >> 4, kp = (c & 15) * 8;
        *(uint4*)(sm + SM_W1 + row * 272 + kp * 2) =
            *(const uint4*)(g_W1f + row * 128 + kp);
    }
    for (int c = tid; c < 4096; c += 512) {
        int row = c >> 5, kp = (c & 31) * 8;
        *(uint4*)(sm + SM_W2 + row * 528 + kp * 2) =
            *(const uint4*)(g_W2f + row * 256 + kp);
    }
    if (tid < 128) sB1b[tid] = b1b[tid];

    {
        const int e0 = blockIdx.x * 128;
        if (tid < 128) { sEi[0][tid] = ei[e0 + tid]; sCd[0][tid] = ei[NE + e0 + tid]; }
#pragma unroll
        for (int j = 0; j < 8; j++) {
            int idx = tid + j * 512;
            int m = idx >> 5, q = idx & 31;
            float4 v = ((const float4*)(ea + (size_t)(e0 + m) * 128))[q];
            uint32_t h0 = f2h2(make_float2(v.x, v.y));
            uint32_t h1 = f2h2(make_float2(v.z, v.w));
            *(uint2*)(sm + SM_AH + (m * 136 + q * 4) * 2) = make_uint2(h0, h1);
        }
    }

    int it = 0;
    for (int tile = blockIdx.x; tile < NTILES; tile += gridDim.x, it ^= 1) {
        __syncthreads();

        float c1[2][8][4];
#pragma unroll
        for (int mt = 0; mt < 2; mt++)
#pragma unroll
            for (int nt = 0; nt < 8; nt++)
#pragma unroll
                for (int q = 0; q < 4; q++) c1[mt][nt][q] = 0.f;

#pragma unroll 2
        for (int kc = 0; kc < 8; kc++) {
            const int kg = kc * 16;
            uint32_t af[2][4];
#pragma unroll
            for (int mt = 0; mt < 2; mt++) {
                const __half* hb = sAH + (wm * 32 + mt * 16 + rbase) * 136 + kg + cpos;
                af[mt][0] = *(const uint32_t*)(hb);
                af[mt][1] = *(const uint32_t*)(hb + 8 * 136);
                af[mt][2] = *(const uint32_t*)(hb + 8);
                af[mt][3] = *(const uint32_t*)(hb + 8 * 136 + 8);
            }
            uint32_t bf[8][2];
#pragma unroll
            for (int ntp = 0; ntp < 4; ntp++) {
                uint32_t off = (uint32_t)(wn * 64 + ntp * 16 + gn + r8) * 272
                             + (uint32_t)(kg + gk) * 2;
                ldmx4(bf[2*ntp][0], bf[2*ntp][1], bf[2*ntp+1][0], bf[2*ntp+1][1], uW1 + off);
            }
#pragma unroll
            for (int mt = 0; mt < 2; mt++)
#pragma unroll
                for (int nt = 0; nt < 8; nt++)
                    mma_f16(c1[mt][nt], af[mt], bf[nt]);
        }
        __syncthreads();

#pragma unroll
        for (int mt = 0; mt < 2; mt++) {
            int r0 = wm * 32 + mt * 16 + rbase, r1 = r0 + 8;
            const float* P0 = g_P + (size_t)sEi[it][r0] * 256;
            const float* P1 = g_P + (size_t)sEi[it][r1] * 256;
#pragma unroll
            for (int nt = 0; nt < 8; nt++) {
                int col = wn * 64 + nt * 8 + cpos;
                float2 q0 = *(const float2*)(P0 + col);
                float2 q1 = *(const float2*)(P1 + col);
                float2 v0, v1;
                v0.x = fmaxf(c1[mt][nt][0] + q0.x, 0.f);
                v0.y = fmaxf(c1[mt][nt][1] + q0.y, 0.f);
                v1.x = fmaxf(c1[mt][nt][2] + q1.x, 0.f);
                v1.y = fmaxf(c1[mt][nt][3] + q1.y, 0.f);
                *(uint32_t*)(sAH + r0 * 264 + col) = f2h2(v0);
                *(uint32_t*)(sAH + r1 * 264 + col) = f2h2(v1);
            }
        }
        __syncthreads();

        const int ntile = tile + gridDim.x;
        const bool hn = ntile < NTILES;
        float4 pref[8];
        if (hn) {
            const int e0n = ntile * 128;
#pragma unroll
            for (int j = 0; j < 8; j++) {
                int idx = tid + j * 512;
                int m = idx >> 5, q = idx & 31;
                pref[j] = ((const float4*)(ea + (size_t)(e0n + m) * 128))[q];
            }
            if (tid < 128) {
                sEi[it ^ 1][tid] = ei[e0n + tid];
                sCd[it ^ 1][tid] = ei[NE + e0n + tid];
            }
        }

        float c2[2][4][4];
#pragma unroll
        for (int mt = 0; mt < 2; mt++)
#pragma unroll
            for (int nt = 0; nt < 4; nt++)
#pragma unroll
                for (int q = 0; q < 4; q++) c2[mt][nt][q] = 0.f;

#pragma unroll 2
        for (int kc = 0; kc < 16; kc++) {
            const int kg = kc * 16;
            uint32_t af[2][4];
#pragma unroll
            for (int mt = 0; mt < 2; mt++) {
                const __half* hb = sAH + (wm * 32 + mt * 16 + rbase) * 264 + kg + cpos;
                af[mt][0] = *(const uint32_t*)(hb);
                af[mt][1] = *(const uint32_t*)(hb + 8 * 264);
                af[mt][2] = *(const uint32_t*)(hb + 8);
                af[mt][3] = *(const uint32_t*)(hb + 8 * 264 + 8);
            }
            uint32_t bf[4][2];
#pragma unroll
            for (int ntp = 0; ntp < 2; ntp++) {
                uint32_t off = (uint32_t)(wn * 32 + ntp * 16 + gn + r8) * 528
                             + (uint32_t)(kg + gk) * 2;
                ldmx4(bf[2*ntp][0], bf[2*ntp][1], bf[2*ntp+1][0], bf[2*ntp+1][1], uW2 + off);
            }
#pragma unroll
            for (int mt = 0; mt < 2; mt++)
#pragma unroll
                for (int nt = 0; nt < 4; nt++)
                    mma_f16(c2[mt][nt], af[mt], bf[nt]);
        }
        __syncthreads();

        if (hn) {
#pragma unroll
            for (int j = 0; j < 8; j++) {
                int idx = tid + j * 512;
                int m = idx >> 5, q = idx & 31;
                uint32_t h0 = f2h2(make_float2(pref[j].x, pref[j].y));
                uint32_t h1 = f2h2(make_float2(pref[j].z, pref[j].w));
                *(uint2*)(sm + SM_AH + (m * 136 + q * 4) * 2) = make_uint2(h0, h1);
            }
        }

#pragma unroll
        for (int mt = 0; mt < 2; mt++) {
            int r0 = wm * 32 + mt * 16 + rbase, r1 = r0 + 8;
            float* s0 = g_sum + (size_t)sCd[it][r0] * 128;
            float* s1 = g_sum + (size_t)sCd[it][r1] * 128;
#pragma unroll
            for (int nt = 0; nt < 4; nt++) {
                int col = wn * 32 + nt * 8 + cpos;
                atomicAdd(s0 + col,     c2[mt][nt][0] + sB1b[col]);
                atomicAdd(s0 + col + 1, c2[mt][nt][1] + sB1b[col + 1]);
                atomicAdd(s1 + col,     c2[mt][nt][2] + sB1b[col]);
                atomicAdd(s1 + col + 1, c2[mt][nt][3] + sB1b[col + 1]);
            }
        }
        if (wn == 0 && (lane & 3) == 0) {
#pragma unroll
            for (int q = 0; q < 4; q++)
                atomicAdd(&g_cnt[sCd[it][wm * 32 + q * 8 + rbase]], 1);
        }
    }
}

// ============================================================================
// Persistent pt kernel: 512 threads, 128 rows/tile, W1t+W2t resident.
//   P = x @ W1t^T + b1a ;  T = x @ W2t^T + b2a
// ============================================================================
#define PT_AH  0          // A fp16 [128][136] = 34816
#define PT_W1  34816      // [256][136] = 69632
#define PT_W2  104448     // [256][136] = 69632
#define PT_BA  174080     // float[256]
#define PT_BB  175104     // float[256]
#define SMEM_PT 176128
#define NT_PT  ((NN + 127) / 128)   // 391

__global__ __launch_bounds__(512, 1)
void pt_tc(const float* __restrict__ x,
           const float* __restrict__ b1a,
           const float* __restrict__ b2a) {
    extern __shared__ char sm[];
    __half* sAH = (__half*)(sm + PT_AH);
    float* sBa = (float*)(sm + PT_BA);
    float* sBb = (float*)(sm + PT_BB);
    const uint32_t sbase = smem_u32(sm);
    const uint32_t uW1 = sbase + PT_W1, uW2 = sbase + PT_W2;

    const int tid = threadIdx.x, lane = tid & 31, wid = tid >> 5;
    const int wm = wid & 3, wn = wid >> 2;
    const int rbase = lane >> 2, cpos = 2 * (lane & 3);
    const int g = lane >> 3, r8 = lane & 7;
    const int gk = (g & 1) << 3, gn = (g >> 1) << 3;

    for (int c = tid; c < 4096; c += 512) {
        int row = c >> 4, kp = (c & 15) * 8;
        *(uint4*)(sm + PT_W1 + row * 272 + kp * 2) =
            *(const uint4*)(g_W1t + row * 128 + kp);
        *(uint4*)(sm + PT_W2 + row * 272 + kp * 2) =
            *(const uint4*)(g_W2t + row * 128 + kp);
    }
    if (tid < 256) { sBa[tid] = b1a[tid]; sBb[tid] = b2a[tid]; }

    for (int tile = blockIdx.x; tile < NT_PT; tile += gridDim.x) {
        const int m0 = tile * 128;
        // A tile: x fp32 -> fp16, stride 136 halfs, guarded
#pragma unroll
        for (int j = 0; j < 8; j++) {
            int idx = tid + j * 512;
            int m = idx >> 5, q = idx & 31;
            int gm = m0 + m;
            float4 v = make_float4(0.f, 0.f, 0.f, 0.f);
            if (gm < NN) v = ((const float4*)(x + (size_t)gm * 128))[q];
            uint32_t h0 = f2h2(make_float2(v.x, v.y));
            uint32_t h1 = f2h2(make_float2(v.z, v.w));
            *(uint2*)(sm + PT_AH + (m * 136 + q * 4) * 2) = make_uint2(h0, h1);
        }
        __syncthreads();

#pragma unroll
        for (int ph = 0; ph < 2; ph++) {
            const uint32_t uW = ph ? uW2 : uW1;
            const float* bias = ph ? sBb : sBa;
            float* dst = ph ? g_T : g_P;

            float c1[2][8][4];
#pragma unroll
            for (int mt = 0; mt < 2; mt++)
#pragma unroll
                for (int nt = 0; nt < 8; nt++)
#pragma unroll
                    for (int q = 0; q < 4; q++) c1[mt][nt][q] = 0.f;

#pragma unroll 2
            for (int kc = 0; kc < 8; kc++) {
                const int kg = kc * 16;
                uint32_t af[2][4];
#pragma unroll
                for (int mt = 0; mt < 2; mt++) {
                    const __half* hb = sAH + (wm * 32 + mt * 16 + rbase) * 136 + kg + cpos;
                    af[mt][0] = *(const uint32_t*)(hb);
                    af[mt][1] = *(const uint32_t*)(hb + 8 * 136);
                    af[mt][2] = *(const uint32_t*)(hb + 8);
                    af[mt][3] = *(const uint32_t*)(hb + 8 * 136 + 8);
                }
                uint32_t bf[8][2];
#pragma unroll
                for (int ntp = 0; ntp < 4; ntp++) {
                    uint32_t off = (uint32_t)(wn * 64 + ntp * 16 + gn + r8) * 272
                                 + (uint32_t)(kg + gk) * 2;
                    ldmx4(bf[2*ntp][0], bf[2*ntp][1], bf[2*ntp+1][0], bf[2*ntp+1][1], uW + off);
                }
#pragma unroll
                for (int mt = 0; mt < 2; mt++)
#pragma unroll
                    for (int nt = 0; nt < 8; nt++)
                        mma_f16(c1[mt][nt], af[mt], bf[nt]);
            }

#pragma unroll
            for (int mt = 0; mt < 2; mt++) {
                int r0 = wm * 32 + mt * 16 + rbase, r1 = r0 + 8;
                int gm0 = m0 + r0, gm1 = m0 + r1;
#pragma unroll
                for (int nt = 0; nt < 8; nt++) {
                    int col = wn * 64 + nt * 8 + cpos;
                    if (gm0 < NN) {
                        float2 v; v.x = c1[mt][nt][0] + bias[col]; v.y = c1[mt][nt][1] + bias[col + 1];
                        *(float2*)(dst + (size_t)gm0 * 256 + col) = v;
                    }
                    if (gm1 < NN) {
                        float2 v; v.x = c1[mt][nt][2] + bias[col]; v.y = c1[mt][nt][3] + bias[col + 1];
                        *(float2*)(dst + (size_t)gm1 * 256 + col) = v;
                    }
                }
            }
        }
        __syncthreads();   // all reads of sAH done before next tile overwrites
    }
}

// ============================================================================
// Persistent node kernel: 512 threads, 128 nodes/tile, W2m+W2bT resident.
//   C1 = agg @ W2m^T (K=128); h = relu(C1 + T + UG[batch]) -> H
//   C2 = h @ W2bT^T (K=256) ; out = C2 + b2b
// ============================================================================
#define ND_AH  0          // A fp16 [128][136]=34816 ; H fp16 [128][264]=67584
#define ND_W1  67584      // W2m [256][136] = 69632
#define ND_W2  137216     // W2bT [128][264] = 67584
#define ND_BT  204800     // int[128]
#define ND_B2B 205312     // float[128]
#define SMEM_N 205824

__global__ __launch_bounds__(512, 1)
void node_tc(const int* __restrict__ batch,
             const float* __restrict__ b2b,
             float* __restrict__ out) {
    extern __shared__ char sm[];
    __half* sAH = (__half*)(sm + ND_AH);
    int*    sBt = (int*)(sm + ND_BT);
    float*  sB2b= (float*)(sm + ND_B2B);
    const uint32_t sbase = smem_u32(sm);
    const uint32_t uW1 = sbase + ND_W1, uW2 = sbase + ND_W2;

    const int tid = threadIdx.x, lane = tid & 31, wid = tid >> 5;
    const int wm = wid & 3, wn = wid >> 2;
    const int rbase = lane >> 2, cpos = 2 * (lane & 3);
    const int g = lane >> 3, r8 = lane & 7;
    const int gk = (g & 1) << 3, gn = (g >> 1) << 3;

    for (int c = tid; c < 4096; c += 512) {
        int row = c >> 4, kp = (c & 15) * 8;
        *(uint4*)(sm + ND_W1 + row * 272 + kp * 2) =
            *(const uint4*)(g_W2m + row * 128 + kp);
    }
    for (int c = tid; c < 4096; c += 512) {
        int row = c >> 5, kp = (c & 31) * 8;
        *(uint4*)(sm + ND_W2 + row * 528 + kp * 2) =
            *(const uint4*)(g_W2bT + row * 256 + kp);
    }
    if (tid < 128) sB2b[tid] = b2b[tid];

    for (int tile = blockIdx.x; tile < NT_PT; tile += gridDim.x) {
        const int m0 = tile * 128;
        if (tid < 128) sBt[tid] = (m0 + tid < NN) ? batch[m0 + tid] : 0;
        // agg tile: g_sum/cnt -> fp16, stride 136 halfs, guarded
#pragma unroll
        for (int j = 0; j < 8; j++) {
            int idx = tid + j * 512;
            int m = idx >> 5, q = idx & 31;
            int gm = m0 + m;
            float4 v = make_float4(0.f, 0.f, 0.f, 0.f);
            if (gm < NN) {
                float sc = 1.0f / fmaxf((float)g_cnt[gm], 1.0f);
                float4 s = ((const float4*)(g_sum + (size_t)gm * 128))[q];
                v.x = s.x * sc; v.y = s.y * sc; v.z = s.z * sc; v.w = s.w * sc;
            }
            uint32_t h0 = f2h2(make_float2(v.x, v.y));
            uint32_t h1 = f2h2(make_float2(v.z, v.w));
            *(uint2*)(sm + ND_AH + (m * 136 + q * 4) * 2) = make_uint2(h0, h1);
        }
        __syncthreads();

        // phase 1
        float c1[2][8][4];
#pragma unroll
        for (int mt = 0; mt < 2; mt++)
#pragma unroll
            for (int nt = 0; nt < 8; nt++)
#pragma unroll
                for (int q = 0; q < 4; q++) c1[mt][nt][q] = 0.f;

#pragma unroll 2
        for (int kc = 0; kc < 8; kc++) {
            const int kg = kc * 16;
            uint32_t af[2][4];
#pragma unroll
            for (int mt = 0; mt < 2; mt++) {
                const __half* hb = sAH + (wm * 32 + mt * 16 + rbase) * 136 + kg + cpos;
                af[mt][0] = *(const uint32_t*)(hb);
                af[mt][1] = *(const uint32_t*)(hb + 8 * 136);
                af[mt][2] = *(const uint32_t*)(hb + 8);
                af[mt][3] = *(const uint32_t*)(hb + 8 * 136 + 8);
            }
            uint32_t bf[8][2];
#pragma unroll
            for (int ntp = 0; ntp < 4; ntp++) {
                uint32_t off = (uint32_t)(wn * 64 + ntp * 16 + gn + r8) * 272
                             + (uint32_t)(kg + gk) * 2;
                ldmx4(bf[2*ntp][0], bf[2*ntp][1], bf[2*ntp+1][0], bf[2*ntp+1][1], uW1 + off);
            }
#pragma unroll
            for (int mt = 0; mt < 2; mt++)
#pragma unroll
                for (int nt = 0; nt < 8; nt++)
                    mma_f16(c1[mt][nt], af[mt], bf[nt]);
        }
        __syncthreads();

        // epi 1: h = relu(C1 + T + UG[batch]) -> H fp16 [128][264]
#pragma unroll
        for (int mt = 0; mt < 2; mt++) {
            int r0 = wm * 32 + mt * 16 + rbase, r1 = r0 + 8;
            int gm0 = m0 + r0, gm1 = m0 + r1;
            const float* T0 = g_T + (size_t)gm0 * 256;
            const float* T1 = g_T + (size_t)gm1 * 256;
            const float* U0 = g_UG + (size_t)sBt[r0] * 256;
            const float* U1 = g_UG + (size_t)sBt[r1] * 256;
#pragma unroll
            for (int nt = 0; nt < 8; nt++) {
                int col = wn * 64 + nt * 8 + cpos;
                float2 v0 = make_float2(0.f, 0.f), v1 = make_float2(0.f, 0.f);
                if (gm0 < NN) {
                    float2 t = *(const float2*)(T0 + col);
                    float2 ug = *(const float2*)(U0 + col);
                    v0.x = fmaxf(c1[mt][nt][0] + t.x + ug.x, 0.f);
                    v0.y = fmaxf(c1[mt][nt][1] + t.y + ug.y, 0.f);
                }
                if (gm1 < NN) {
                    float2 t = *(const float2*)(T1 + col);
                    float2 ug = *(const float2*)(U1 + col);
                    v1.x = fmaxf(c1[mt][nt][2] + t.x + ug.x, 0.f);
                    v1.y = fmaxf(c1[mt][nt][3] + t.y + ug.y, 0.f);
                }
                *(uint32_t*)(sAH + r0 * 264 + col) = f2h2(v0);
                *(uint32_t*)(sAH + r1 * 264 + col) = f2h2(v1);
            }
        }
        __syncthreads();

        // phase 2
        float c2[2][4][4];
#pragma unroll
        for (int mt = 0; mt < 2; mt++)
#pragma unroll
            for (int nt = 0; nt < 4; nt++)
#pragma unroll
                for (int q = 0; q < 4; q++) c2[mt][nt][q] = 0.f;

#pragma unroll 2
        for (int kc = 0; kc < 16; kc++) {
            const int kg = kc * 16;
            uint32_t af[2][4];
#pragma unroll
            for (int mt = 0; mt < 2; mt++) {
                const __half* hb = sAH + (wm * 32 + mt * 16 + rbase) * 264 + kg + cpos;
                af[mt][0] = *(const uint32_t*)(hb);
                af[mt][1] = *(const uint32_t*)(hb + 8 * 264);
                af[mt][2] = *(const uint32_t*)(hb + 8);
                af[mt][3] = *(const uint32_t*)(hb + 8 * 264 + 8);
            }
            uint32_t bf[4][2];
#pragma unroll
            for (int ntp = 0; ntp < 2; ntp++) {
                uint32_t off = (uint32_t)(wn * 32 + ntp * 16 + gn + r8) * 528
                             + (uint32_t)(kg + gk) * 2;
                ldmx4(bf[2*ntp][0], bf[2*ntp][1], bf[2*ntp+1][0], bf[2*ntp+1][1], uW2 + off);
            }
#pragma unroll
            for (int mt = 0; mt < 2; mt++)
#pragma unroll
                for (int nt = 0; nt < 4; nt++)
                    mma_f16(c2[mt][nt], af[mt], bf[nt]);
        }

        // epi 2: out = C2 + b2b
#pragma unroll
        for (int mt = 0; mt < 2; mt++) {
            int r0 = wm * 32 + mt * 16 + rbase, r1 = r0 + 8;
            int gm0 = m0 + r0, gm1 = m0 + r1;
#pragma unroll
            for (int nt = 0; nt < 4; nt++) {
                int col = wn * 32 + nt * 8 + cpos;
                if (gm0 < NN) {
                    float2 v; v.x = c2[mt][nt][0] + sB2b[col]; v.y = c2[mt][nt][1] + sB2b[col + 1];
                    *(float2*)(out + (size_t)gm0 * 128 + col) = v;
                }
                if (gm1 < NN) {
                    float2 v; v.x = c2[mt][nt][2] + sB2b[col]; v.y = c2[mt][nt][3] + sB2b[col + 1];
                    *(float2*)(out + (size_t)gm1 * 128 + col) = v;
                }
            }
        }
        __syncthreads();   // H reads done before next tile's A load
    }
}

// ============================================================================
// init: zero accumulators + transposed fp16 weights + UG (fp32 exact)
// ============================================================================
__global__ void init_kernel(const float* __restrict__ W1a, const float* __restrict__ W1b,
                            const float* __restrict__ W2a, const float* __restrict__ W2b,
                            const float* __restrict__ u) {
    int i = blockIdx.x * blockDim.x + threadIdx.x;
    int st = gridDim.x * blockDim.x;
    float4 z = make_float4(0.f, 0.f, 0.f, 0.f);
    for (int idx = i; idx < NN * 32; idx += st) ((float4*)g_sum)[idx] = z;
    for (int idx = i; idx < NN; idx += st) g_cnt[idx] = 0;
    for (int idx = i; idx < 256 * 128; idx += st) {
        int n = idx >> 7, k = idx & 127;
        g_W1f[idx] = __float2half_rn(W1a[(128 + k) * 256 + n]);
        g_W1t[idx] = __float2half_rn(W1a[k * 256 + n]);
        g_W2t[idx] = __float2half_rn(W2a[k * 256 + n]);
        g_W2m[idx] = __float2half_rn(W2a[(128 + k) * 256 + n]);
    }
    for (int idx = i; idx < 128 * 256; idx += st) {
        int n = idx >> 8, k = idx & 255;
        g_W2f[idx]  = __float2half_rn(W1b[k * 128 + n]);
        g_W2bT[idx] = __float2half_rn(W2b[k * 128 + n]);
    }
    // UG = u @ W2a[256:384,:]  fp32 exact
    for (int idx = i; idx < NG * 256; idx += st) {
        int m = idx >> 8, n = idx & 255;
        float s = 0.f;
#pragma unroll 4
        for (int k = 0; k < 128; k++)
            s += u[m * 128 + k] * W2a[(256 + k) * 256 + n];
        g_UG[idx] = s;
    }
}

// ============================================================================
extern "C" void kernel_launch(void* const* d_in, const int* in_sizes, int n_in,
                              void* d_out, int out_size) {
    const float* x     = (const float*)d_in[0];
    const int*   ei    = (const int*)d_in[1];     // int32 (JAX x64 disabled)
    const float* ea    = (const float*)d_in[2];
    const float* u     = (const float*)d_in[3];
    const int*   batch = (const int*)d_in[4];
    const float* W1a   = (const float*)d_in[5];
    const float* b1a   = (const float*)d_in[6];
    const float* W1b   = (const float*)d_in[7];
    const float* b1b   = (const float*)d_in[8];
    const float* W2a   = (const float*)d_in[9];
    const float* b2a   = (const float*)d_in[10];
    const float* W2b   = (const float*)d_in[11];
    const float* b2b   = (const float*)d_in[12];
    float* out = (float*)d_out;

    cudaFuncSetAttribute(edge_tc, cudaFuncAttributeMaxDynamicSharedMemorySize, SMEM_E);
    cudaFuncSetAttribute(pt_tc,   cudaFuncAttributeMaxDynamicSharedMemorySize, SMEM_PT);
    cudaFuncSetAttribute(node_tc, cudaFuncAttributeMaxDynamicSharedMemorySize, SMEM_N);

    init_kernel<<<128, 256>>>(W1a, W1b, W2a, W2b, u);

    pt_tc<<<EDGE_GRID, 512, SMEM_PT>>>(x, b1a, b2a);

    edge_tc<<<EDGE_GRID, 512, SMEM_E>>>(ea, ei, b1b);

    node_tc<<<EDGE_GRID, 512, SMEM_N>>>(batch, b2b, out);
}